// round 6
// baseline (speedup 1.0000x reference)
#include <cuda_runtime.h>
#include <cuda_bf16.h>
#include <math.h>
#include <stdint.h>

#define NW    2048
#define NBINS 1024
#define NH    16
#define HD    64

// ---------------- scratch (device globals: allocation-free) ----------------
__device__ float g_lin[3][NW][NBINS];          // post-projection q/k/v (pre-conv)
__device__ float g_v[NW][NBINS];               // post-conv V fp32
__device__ __nv_bfloat16 g_qb[NW][NBINS];      // post-conv Q, bf16
__device__ __nv_bfloat16 g_kb[NW][NBINS];      // post-conv K, bf16
__device__ __nv_bfloat16 g_rwb[NW][HD];        // relw^T bf16
__device__ __nv_bfloat16 g_vth[NH][HD][NW];    // V^T per head, hi part
__device__ __nv_bfloat16 g_vtl[NH][HD][NW];    // V^T per head, lo part
__device__ float g_o[NW][NBINS];               // attention output (pre-Wo)

// ======================= PTX helpers (generic sm_80+) ======================
__device__ __forceinline__ uint32_t smem_u32(const void* p) {
    uint32_t a;
    asm("{ .reg .u64 t; cvta.to.shared.u64 t, %1; cvt.u32.u64 %0, t; }"
        : "=r"(a) : "l"(p));
    return a;
}
__device__ __forceinline__ void ldm_x4(uint32_t r[4], uint32_t addr) {
    asm volatile("ldmatrix.sync.aligned.m8n8.x4.shared.b16 {%0,%1,%2,%3}, [%4];"
                 : "=r"(r[0]), "=r"(r[1]), "=r"(r[2]), "=r"(r[3]) : "r"(addr));
}
__device__ __forceinline__ void ldm_x4_t(uint32_t r[4], uint32_t addr) {
    asm volatile("ldmatrix.sync.aligned.m8n8.x4.trans.shared.b16 {%0,%1,%2,%3}, [%4];"
                 : "=r"(r[0]), "=r"(r[1]), "=r"(r[2]), "=r"(r[3]) : "r"(addr));
}
__device__ __forceinline__ void mma_16816(float c[4], const uint32_t a[4],
                                          uint32_t b0, uint32_t b1) {
    asm volatile(
        "mma.sync.aligned.m16n8k16.row.col.f32.bf16.bf16.f32 "
        "{%0,%1,%2,%3}, {%4,%5,%6,%7}, {%8,%9}, {%0,%1,%2,%3};"
        : "+f"(c[0]), "+f"(c[1]), "+f"(c[2]), "+f"(c[3])
        : "r"(a[0]), "r"(a[1]), "r"(a[2]), "r"(a[3]), "r"(b0), "r"(b1));
}
// pack two floats as bf16x2: lo -> bits [0:16), hi -> bits [16:32)
__device__ __forceinline__ uint32_t pack_bf16(float lo, float hi) {
    uint32_t r;
    asm("cvt.rn.bf16x2.f32 %0, %1, %2;" : "=r"(r) : "f"(hi), "f"(lo));
    return r;
}
// split a float4 into hi/lo bf16 quads and store (8B each)
__device__ __forceinline__ void split_store(float4 v, __nv_bfloat16* ph,
                                            __nv_bfloat16* pl) {
    __nv_bfloat16 hh[4], ll[4];
#pragma unroll
    for (int i = 0; i < 4; i++) {
        float f = (&v.x)[i];
        hh[i] = __float2bfloat16(f);
        ll[i] = __float2bfloat16(f - __bfloat162float(hh[i]));
    }
    *(uint2*)ph = *(uint2*)hh;
    *(uint2*)pl = *(uint2*)ll;
}

// ================= split-bf16 tensor GEMM: C = A(2048x1024) @ B(1024x1024) ==
#define GS_SMEM 71680
__device__ __forceinline__ void gemm_split(const float* __restrict__ A,
                                           const float* __restrict__ B,
                                           float* __restrict__ C)
{
    extern __shared__ __nv_bfloat16 gs[];
    __nv_bfloat16* sAh = gs;                // [128][72]
    __nv_bfloat16* sAl = gs + 9216;
    __nv_bfloat16* sBh = gs + 18432;        // [64][136]  (k-major)
    __nv_bfloat16* sBl = gs + 27136;
    const int t = threadIdx.x, wid = t >> 5, lane = t & 31;
    const int m0 = blockIdx.y * 128, n0 = blockIdx.x * 128;
    const int wm = wid >> 1, wn = wid & 1;  // warp tile 32(m) x 64(n)

    float acc[2][8][4];
#pragma unroll
    for (int mi = 0; mi < 2; mi++)
#pragma unroll
        for (int o = 0; o < 8; o++)
#pragma unroll
            for (int e = 0; e < 4; e++) acc[mi][o][e] = 0.f;

    for (int k0 = 0; k0 < 1024; k0 += 64) {
#pragma unroll
        for (int s = 0; s < 8; s++) {                 // A 128x64
            int e = t + 256 * s;
            int r = e >> 4, c4 = e & 15;
            float4 a = *(const float4*)&A[(size_t)(m0 + r) * 1024 + k0 + c4 * 4];
            split_store(a, &sAh[r * 72 + c4 * 4], &sAl[r * 72 + c4 * 4]);
        }
#pragma unroll
        for (int s = 0; s < 8; s++) {                 // B 64x128
            int e = t + 256 * s;
            int kr = e >> 5, c4 = e & 31;
            float4 b = *(const float4*)&B[(size_t)(k0 + kr) * 1024 + n0 + c4 * 4];
            split_store(b, &sBh[kr * 136 + c4 * 4], &sBl[kr * 136 + c4 * 4]);
        }
        __syncthreads();
        const uint32_t bAh = smem_u32(sAh), bAl = smem_u32(sAl);
        const uint32_t bBh = smem_u32(sBh), bBl = smem_u32(sBl);
        const int g = lane >> 3;
#pragma unroll
        for (int kk = 0; kk < 64; kk += 16) {
            uint32_t ah[2][4], al[2][4], bb[8][2];
#pragma unroll
            for (int mi = 0; mi < 2; mi++) {
                uint32_t off = (uint32_t)((wm * 32 + mi * 16 + (lane & 15)) * 72
                                          + kk + (lane >> 4) * 8) * 2;
                ldm_x4(ah[mi], bAh + off);
                ldm_x4(al[mi], bAl + off);
            }
#pragma unroll
            for (int g4 = 0; g4 < 4; g4++) {          // B hi frags via trans
                uint32_t off = (uint32_t)((kk + (g >> 1) * 8 + (lane & 7)) * 136
                                          + wn * 64 + g4 * 16 + (g & 1) * 8) * 2;
                uint32_t r4[4];
                ldm_x4_t(r4, bBh + off);
                bb[g4 * 2 + 0][0] = r4[0]; bb[g4 * 2 + 0][1] = r4[2];
                bb[g4 * 2 + 1][0] = r4[1]; bb[g4 * 2 + 1][1] = r4[3];
            }
#pragma unroll
            for (int mi = 0; mi < 2; mi++)
#pragma unroll
                for (int o = 0; o < 8; o++)
                    mma_16816(acc[mi][o], ah[mi], bb[o][0], bb[o][1]);
#pragma unroll
            for (int mi = 0; mi < 2; mi++)
#pragma unroll
                for (int o = 0; o < 8; o++)
                    mma_16816(acc[mi][o], al[mi], bb[o][0], bb[o][1]);
#pragma unroll
            for (int g4 = 0; g4 < 4; g4++) {          // B lo frags
                uint32_t off = (uint32_t)((kk + (g >> 1) * 8 + (lane & 7)) * 136
                                          + wn * 64 + g4 * 16 + (g & 1) * 8) * 2;
                uint32_t r4[4];
                ldm_x4_t(r4, bBl + off);
                bb[g4 * 2 + 0][0] = r4[0]; bb[g4 * 2 + 0][1] = r4[2];
                bb[g4 * 2 + 1][0] = r4[1]; bb[g4 * 2 + 1][1] = r4[3];
            }
#pragma unroll
            for (int mi = 0; mi < 2; mi++)
#pragma unroll
                for (int o = 0; o < 8; o++)
                    mma_16816(acc[mi][o], ah[mi], bb[o][0], bb[o][1]);
        }
        __syncthreads();
    }
#pragma unroll
    for (int mi = 0; mi < 2; mi++)
#pragma unroll
        for (int o = 0; o < 8; o++)
#pragma unroll
            for (int half = 0; half < 2; half++) {
                int row = m0 + wm * 32 + mi * 16 + (lane >> 2) + half * 8;
                int col = n0 + wn * 64 + o * 8 + (lane & 3) * 2;
                float2 w;
                w.x = acc[mi][o][half * 2 + 0];
                w.y = acc[mi][o][half * 2 + 1];
                *(float2*)&C[(size_t)row * 1024 + col] = w;
            }
}

// K1: q/k/v projections (tensor, split-bf16)
__global__ void __launch_bounds__(256, 2)
proj_mma_kernel(const float* __restrict__ x, const float* __restrict__ Wq,
                const float* __restrict__ Wk, const float* __restrict__ Wv)
{
    const float* B = (blockIdx.z == 0) ? Wq : (blockIdx.z == 1 ? Wk : Wv);
    gemm_split(x, B, &g_lin[blockIdx.z][0][0]);
}

// K6: out = g_o @ Wo (tensor, split-bf16)
__global__ void __launch_bounds__(256, 2)
out_mma_kernel(const float* __restrict__ Wo, float* __restrict__ out)
{
    gemm_split(&g_o[0][0], Wo, out);
}

// K2: depthwise conv; Q,K as bf16, V fp32
__global__ void conv_kernel(const float* __restrict__ cq,
                            const float* __restrict__ ck,
                            const float* __restrict__ cv)
{
    int idx = blockIdx.x * 256 + threadIdx.x;
    int z   = idx / (NW * NBINS);
    int rem = idx - z * (NW * NBINS);
    int w   = rem >> 10;
    int c   = rem & 1023;
    const float* cw = (z == 0) ? cq : (z == 1 ? ck : cv);
    float w0 = cw[c * 3 + 0], w1 = cw[c * 3 + 1], w2 = cw[c * 3 + 2];
    float acc = g_lin[z][w][c] * w1;
    if (w > 0)      acc += g_lin[z][w - 1][c] * w0;
    if (w < NW - 1) acc += g_lin[z][w + 1][c] * w2;
    if (z == 0)      g_qb[w][c] = __float2bfloat16(acc);
    else if (z == 1) g_kb[w][c] = __float2bfloat16(acc);
    else             g_v[w][c]  = acc;
}

// K2b: relw transpose + bf16 convert
__global__ void relw_cvt_kernel(const float* __restrict__ relw)
{
    int idx = blockIdx.x * 256 + threadIdx.x;   // 64*2048
    int d = idx >> 11, i = idx & 2047;
    g_rwb[i][d] = __float2bfloat16(relw[idx]);
}

// K2c: V -> per-head transposed hi/lo bf16 (tiled 64x64 transpose)
__global__ void __launch_bounds__(256)
vt_split_kernel()
{
    __shared__ float tile[64][65];
    const int w0 = blockIdx.x * 64, h = blockIdx.y;
    const int t = threadIdx.x;
#pragma unroll
    for (int s = 0; s < 4; s++) {
        int e = t + 256 * s;
        int r = e >> 4, c4 = e & 15;
        float4 v = *(const float4*)&g_v[w0 + r][h * 64 + c4 * 4];
        tile[r][c4 * 4 + 0] = v.x; tile[r][c4 * 4 + 1] = v.y;
        tile[r][c4 * 4 + 2] = v.z; tile[r][c4 * 4 + 3] = v.w;
    }
    __syncthreads();
#pragma unroll
    for (int s = 0; s < 4; s++) {
        int e = t + 256 * s;
        int d = e >> 4, w4 = e & 15;
        __nv_bfloat16 hh[4], ll[4];
#pragma unroll
        for (int i = 0; i < 4; i++) {
            float f = tile[w4 * 4 + i][d];
            hh[i] = __float2bfloat16(f);
            ll[i] = __float2bfloat16(f - __bfloat162float(hh[i]));
        }
        *(uint2*)&g_vth[h][d][w0 + w4 * 4] = *(uint2*)hh;
        *(uint2*)&g_vtl[h][d][w0 + w4 * 4] = *(uint2*)ll;
    }
}

// K3: fused attention. Block = (128-row i-tile, head h). For each 128-col
// j-tile: qk tile via mma.sync (D = Qi@Kj^T + Rwi@Qj^T; qk = D/32 + prev,
// written to gmem), then P = exp(qk) (no max needed: |qk| <~ 1), repack the
// fp32 accumulators into bf16 A-frags (FA register identity) and accumulate
// O += P@V with split-P/split-V 3-term MMAs. Row sums accumulate per thread;
// each warp owns 16 full rows so no cross-warp reduction.
#define AT_SMEM 108544
__global__ void __launch_bounds__(256)
attn_fused_kernel(const float* __restrict__ prev, float* __restrict__ qk)
{
    extern __shared__ __nv_bfloat16 smf[];
    __nv_bfloat16* sQi = smf;                    // [128][72]
    __nv_bfloat16* sRw = smf + 9216;             // [128][72]
    __nv_bfloat16* sKj = smf + 2 * 9216;         // [128][72]
    __nv_bfloat16* sQj = smf + 3 * 9216;         // [128][72]
    __nv_bfloat16* sVh = smf + 4 * 9216;         // [64][136] V^T hi: [d][j]
    __nv_bfloat16* sVl = smf + 4 * 9216 + 8704;  // [64][136] V^T lo

    const int t = threadIdx.x, wid = t >> 5, lane = t & 31;
    const int i0 = blockIdx.x * 128, h = blockIdx.y;
    const int qr = lane >> 2, qc = (lane & 3) * 2;
    const int m0 = wid * 16;                     // warp's 16-row slice

    {   // persistent Qi / Rw tiles
        const int r = t & 127, ch0 = (t >> 7) * 4;
        const uint4* qi = (const uint4*)&g_qb[i0 + r][h * 64];
        const uint4* rw = (const uint4*)&g_rwb[i0 + r][0];
#pragma unroll
        for (int c = 0; c < 4; c++) {
            int c16 = ch0 + c;
            *(uint4*)((char*)sQi + r * 144 + c16 * 16) = qi[c16];
            *(uint4*)((char*)sRw + r * 144 + c16 * 16) = rw[c16];
        }
    }

    float acc_o[8][4];
#pragma unroll
    for (int n = 0; n < 8; n++)
#pragma unroll
        for (int e = 0; e < 4; e++) acc_o[n][e] = 0.f;
    float s0 = 0.f, s1 = 0.f;

    const uint32_t bQi = smem_u32(sQi), bRw = smem_u32(sRw);
    const uint32_t bKj = smem_u32(sKj), bQj = smem_u32(sQj);
    const uint32_t bVh = smem_u32(sVh), bVl = smem_u32(sVl);
    const uint32_t arow = (uint32_t)(m0 + (lane & 15)) * 144;
    const uint32_t brow = (uint32_t)(lane & 15) * 144;
    const uint32_t vrow = (uint32_t)(lane & 15) * 272;
    const float inv = 1.0f / 32.0f;

    for (int jb = 0; jb < 16; jb++) {
        const int j0 = jb * 128;
        __syncthreads();
        {   // per-tile K / Qj / V loads
            const int r = t & 127, ch0 = (t >> 7) * 4;
            const uint4* kj = (const uint4*)&g_kb[j0 + r][h * 64];
            const uint4* qj = (const uint4*)&g_qb[j0 + r][h * 64];
#pragma unroll
            for (int c = 0; c < 4; c++) {
                int c16 = ch0 + c;
                *(uint4*)((char*)sKj + r * 144 + c16 * 16) = kj[c16];
                *(uint4*)((char*)sQj + r * 144 + c16 * 16) = qj[c16];
            }
#pragma unroll
            for (int s = 0; s < 4; s++) {
                int e = t + 256 * s;
                int d = e >> 4, c16 = e & 15;
                *(uint4*)((char*)sVh + d * 272 + c16 * 16) =
                    *(const uint4*)&g_vth[h][d][j0 + c16 * 8];
                *(uint4*)((char*)sVl + d * 272 + c16 * 16) =
                    *(const uint4*)&g_vtl[h][d][j0 + c16 * 8];
            }
        }
        __syncthreads();

#pragma unroll
        for (int hj = 0; hj < 2; hj++) {          // 64-col halves of j-tile
            const int jc0 = hj * 64;
            float c[8][4];
#pragma unroll
            for (int ni = 0; ni < 8; ni++)
#pragma unroll
                for (int e = 0; e < 4; e++) c[ni][e] = 0.f;

#pragma unroll
            for (int term = 0; term < 2; term++) {
                const uint32_t bA = term ? bRw : bQi;
                const uint32_t bB = term ? bQj : bKj;
#pragma unroll
                for (int ks = 0; ks < 4; ks++) {
                    const uint32_t coff = (uint32_t)(ks * 16 + (lane >> 4) * 8) * 2;
                    uint32_t a[4];
                    ldm_x4(a, bA + arow + coff);
#pragma unroll
                    for (int nq = 0; nq < 4; nq++) {
                        uint32_t r4[4];
                        ldm_x4(r4, bB + (uint32_t)(jc0 + nq * 16) * 144 + brow + coff);
                        mma_16816(c[nq * 2 + 0], a, r4[0], r4[2]);
                        mma_16816(c[nq * 2 + 1], a, r4[1], r4[3]);
                    }
                }
            }

            // epilogue: qk = c/32 + prev (store; keep value in c)
#pragma unroll
            for (int ni = 0; ni < 8; ni++) {
#pragma unroll
                for (int hf = 0; hf < 2; hf++) {
                    int row = i0 + m0 + qr + hf * 8;
                    int col = j0 + jc0 + ni * 8 + qc;
                    size_t off = ((size_t)(h * 2048) + row) * 2048 + col;
                    float2 pv = *(const float2*)&prev[off];
                    float o0 = c[ni][hf * 2 + 0] * inv + pv.x;
                    float o1 = c[ni][hf * 2 + 1] * inv + pv.y;
                    c[ni][hf * 2 + 0] = o0;
                    c[ni][hf * 2 + 1] = o1;
                    float2 w; w.x = o0; w.y = o1;
                    *(float2*)&qk[off] = w;
                }
            }

            // AV: 4 k-chunks of 16 j each
#pragma unroll
            for (int tc = 0; tc < 4; tc++) {
                float p[8], ph[8], pl[8];
#pragma unroll
                for (int e = 0; e < 4; e++) {
                    p[e]     = __expf(c[tc * 2 + 0][e]);
                    p[4 + e] = __expf(c[tc * 2 + 1][e]);
                }
                s0 += p[0] + p[1] + p[4] + p[5];
                s1 += p[2] + p[3] + p[6] + p[7];
#pragma unroll
                for (int e = 0; e < 8; e++) {
                    __nv_bfloat16 b = __float2bfloat16(p[e]);
                    ph[e] = __bfloat162float(b);
                    pl[e] = p[e] - ph[e];
                }
                uint32_t ah[4], al[4];
                ah[0] = pack_bf16(ph[0], ph[1]); ah[1] = pack_bf16(ph[2], ph[3]);
                ah[2] = pack_bf16(ph[4], ph[5]); ah[3] = pack_bf16(ph[6], ph[7]);
                al[0] = pack_bf16(pl[0], pl[1]); al[1] = pack_bf16(pl[2], pl[3]);
                al[2] = pack_bf16(pl[4], pl[5]); al[3] = pack_bf16(pl[6], pl[7]);

                const uint32_t coff = (uint32_t)(jc0 + tc * 16 + (lane >> 4) * 8) * 2;
#pragma unroll
                for (int nq = 0; nq < 4; nq++) {
                    uint32_t r4[4], l4[4];
                    ldm_x4(r4, bVh + (uint32_t)(nq * 16) * 272 + vrow + coff);
                    mma_16816(acc_o[nq * 2 + 0], ah, r4[0], r4[2]);
                    mma_16816(acc_o[nq * 2 + 1], ah, r4[1], r4[3]);
                    mma_16816(acc_o[nq * 2 + 0], al, r4[0], r4[2]);
                    mma_16816(acc_o[nq * 2 + 1], al, r4[1], r4[3]);
                    ldm_x4(l4, bVl + (uint32_t)(nq * 16) * 272 + vrow + coff);
                    mma_16816(acc_o[nq * 2 + 0], ah, l4[0], l4[2]);
                    mma_16816(acc_o[nq * 2 + 1], ah, l4[1], l4[3]);
                }
            }
        }
    }

    // reduce row sums within each 4-lane group (cols of one row)
    s0 += __shfl_xor_sync(0xffffffffu, s0, 1);
    s0 += __shfl_xor_sync(0xffffffffu, s0, 2);
    s1 += __shfl_xor_sync(0xffffffffu, s1, 1);
    s1 += __shfl_xor_sync(0xffffffffu, s1, 2);
    const float r0 = 1.0f / s0, r1 = 1.0f / s1;
#pragma unroll
    for (int n = 0; n < 8; n++) {
        int colb = h * 64 + n * 8 + qc;
        int row = i0 + m0 + qr;
        float2 w0; w0.x = acc_o[n][0] * r0; w0.y = acc_o[n][1] * r0;
        float2 w1; w1.x = acc_o[n][2] * r1; w1.y = acc_o[n][3] * r1;
        *(float2*)&g_o[row][colb] = w0;
        *(float2*)&g_o[row + 8][colb] = w1;
    }
}

// --------------------------------------------------------------------------
extern "C" void kernel_launch(void* const* d_in, const int* in_sizes, int n_in,
                              void* d_out, int out_size)
{
    const float* x    = (const float*)d_in[0];
    const float* prev = (const float*)d_in[1];
    const float* Wq   = (const float*)d_in[2];
    const float* Wk   = (const float*)d_in[3];
    const float* Wv   = (const float*)d_in[4];
    const float* Wo   = (const float*)d_in[5];
    const float* cq   = (const float*)d_in[6];
    const float* ck   = (const float*)d_in[7];
    const float* cv   = (const float*)d_in[8];
    const float* relw = (const float*)d_in[9];

    float* out = (float*)d_out;                 // (1,2048,1024)
    float* qk  = out + (size_t)NW * NBINS;      // (1,16,2048,2048)

    cudaFuncSetAttribute(proj_mma_kernel, cudaFuncAttributeMaxDynamicSharedMemorySize, GS_SMEM);
    cudaFuncSetAttribute(out_mma_kernel,  cudaFuncAttributeMaxDynamicSharedMemorySize, GS_SMEM);
    cudaFuncSetAttribute(attn_fused_kernel, cudaFuncAttributeMaxDynamicSharedMemorySize, AT_SMEM);

    proj_mma_kernel<<<dim3(8, 16, 3), 256, GS_SMEM>>>(x, Wq, Wk, Wv);
    conv_kernel<<<(3 * NW * NBINS) / 256, 256>>>(cq, ck, cv);
    relw_cvt_kernel<<<(HD * NW) / 256, 256>>>(relw);
    vt_split_kernel<<<dim3(32, 16), 256>>>();
    attn_fused_kernel<<<dim3(16, 16), 256, AT_SMEM>>>(prev, qk);
    out_mma_kernel<<<dim3(8, 16), 256, GS_SMEM>>>(Wo, out);
}

// round 7
// speedup vs baseline: 1.2656x; 1.2656x over previous
#include <cuda_runtime.h>
#include <cuda_bf16.h>
#include <math.h>
#include <stdint.h>

#define NW    2048
#define NBINS 1024
#define NH    16
#define HD    64

// ---------------- scratch (device globals: allocation-free) ----------------
__device__ float g_lin[3][NW][NBINS];          // post-projection q/k/v (pre-conv)
__device__ float g_v[NW][NBINS];               // post-conv V fp32
__device__ __nv_bfloat16 g_qb[NW][NBINS];      // post-conv Q, bf16
__device__ __nv_bfloat16 g_kb[NW][NBINS];      // post-conv K, bf16
__device__ __nv_bfloat16 g_rwb[NW][HD];        // relw^T bf16
__device__ __nv_bfloat16 g_vth[NH][HD][NW];    // V^T per head, hi part
__device__ __nv_bfloat16 g_vtl[NH][HD][NW];    // V^T per head, lo part
__device__ float g_o[NW][NBINS];               // attention output (pre-Wo)

// ======================= PTX helpers (generic sm_80+) ======================
__device__ __forceinline__ uint32_t smem_u32(const void* p) {
    uint32_t a;
    asm("{ .reg .u64 t; cvta.to.shared.u64 t, %1; cvt.u32.u64 %0, t; }"
        : "=r"(a) : "l"(p));
    return a;
}
__device__ __forceinline__ void ldm_x4(uint32_t r[4], uint32_t addr) {
    asm volatile("ldmatrix.sync.aligned.m8n8.x4.shared.b16 {%0,%1,%2,%3}, [%4];"
                 : "=r"(r[0]), "=r"(r[1]), "=r"(r[2]), "=r"(r[3]) : "r"(addr));
}
__device__ __forceinline__ void ldm_x4_t(uint32_t r[4], uint32_t addr) {
    asm volatile("ldmatrix.sync.aligned.m8n8.x4.trans.shared.b16 {%0,%1,%2,%3}, [%4];"
                 : "=r"(r[0]), "=r"(r[1]), "=r"(r[2]), "=r"(r[3]) : "r"(addr));
}
__device__ __forceinline__ void mma_16816(float c[4], const uint32_t a[4],
                                          uint32_t b0, uint32_t b1) {
    asm volatile(
        "mma.sync.aligned.m16n8k16.row.col.f32.bf16.bf16.f32 "
        "{%0,%1,%2,%3}, {%4,%5,%6,%7}, {%8,%9}, {%0,%1,%2,%3};"
        : "+f"(c[0]), "+f"(c[1]), "+f"(c[2]), "+f"(c[3])
        : "r"(a[0]), "r"(a[1]), "r"(a[2]), "r"(a[3]), "r"(b0), "r"(b1));
}
// split a float4 into hi/lo bf16 quads and store (8B each)
__device__ __forceinline__ void split_store(float4 v, __nv_bfloat16* ph,
                                            __nv_bfloat16* pl) {
    __nv_bfloat16 hh[4], ll[4];
#pragma unroll
    for (int i = 0; i < 4; i++) {
        float f = (&v.x)[i];
        hh[i] = __float2bfloat16(f);
        ll[i] = __float2bfloat16(f - __bfloat162float(hh[i]));
    }
    *(uint2*)ph = *(uint2*)hh;
    *(uint2*)pl = *(uint2*)ll;
}

// ================= split-bf16 tensor GEMM: C = A(2048x1024) @ B(1024x1024) ==
#define GS_SMEM 71680
__device__ __forceinline__ void gemm_split(const float* __restrict__ A,
                                           const float* __restrict__ B,
                                           float* __restrict__ C)
{
    extern __shared__ __nv_bfloat16 gs[];
    __nv_bfloat16* sAh = gs;                // [128][72]
    __nv_bfloat16* sAl = gs + 9216;
    __nv_bfloat16* sBh = gs + 18432;        // [64][136]  (k-major)
    __nv_bfloat16* sBl = gs + 27136;
    const int t = threadIdx.x, wid = t >> 5, lane = t & 31;
    const int m0 = blockIdx.y * 128, n0 = blockIdx.x * 128;
    const int wm = wid >> 1, wn = wid & 1;  // warp tile 32(m) x 64(n)

    float acc[2][8][4];
#pragma unroll
    for (int mi = 0; mi < 2; mi++)
#pragma unroll
        for (int o = 0; o < 8; o++)
#pragma unroll
            for (int e = 0; e < 4; e++) acc[mi][o][e] = 0.f;

    for (int k0 = 0; k0 < 1024; k0 += 64) {
#pragma unroll
        for (int s = 0; s < 8; s++) {                 // A 128x64
            int e = t + 256 * s;
            int r = e >> 4, c4 = e & 15;
            float4 a = *(const float4*)&A[(size_t)(m0 + r) * 1024 + k0 + c4 * 4];
            split_store(a, &sAh[r * 72 + c4 * 4], &sAl[r * 72 + c4 * 4]);
        }
#pragma unroll
        for (int s = 0; s < 8; s++) {                 // B 64x128
            int e = t + 256 * s;
            int kr = e >> 5, c4 = e & 31;
            float4 b = *(const float4*)&B[(size_t)(k0 + kr) * 1024 + n0 + c4 * 4];
            split_store(b, &sBh[kr * 136 + c4 * 4], &sBl[kr * 136 + c4 * 4]);
        }
        __syncthreads();
        const uint32_t bAh = smem_u32(sAh), bAl = smem_u32(sAl);
        const uint32_t bBh = smem_u32(sBh), bBl = smem_u32(sBl);
        const int g = lane >> 3;
#pragma unroll
        for (int kk = 0; kk < 64; kk += 16) {
            uint32_t ah[2][4], al[2][4], bb[8][2];
#pragma unroll
            for (int mi = 0; mi < 2; mi++) {
                uint32_t off = (uint32_t)((wm * 32 + mi * 16 + (lane & 15)) * 72
                                          + kk + (lane >> 4) * 8) * 2;
                ldm_x4(ah[mi], bAh + off);
                ldm_x4(al[mi], bAl + off);
            }
#pragma unroll
            for (int g4 = 0; g4 < 4; g4++) {          // B hi frags via trans
                uint32_t off = (uint32_t)((kk + (g >> 1) * 8 + (lane & 7)) * 136
                                          + wn * 64 + g4 * 16 + (g & 1) * 8) * 2;
                uint32_t r4[4];
                ldm_x4_t(r4, bBh + off);
                bb[g4 * 2 + 0][0] = r4[0]; bb[g4 * 2 + 0][1] = r4[2];
                bb[g4 * 2 + 1][0] = r4[1]; bb[g4 * 2 + 1][1] = r4[3];
            }
#pragma unroll
            for (int mi = 0; mi < 2; mi++)
#pragma unroll
                for (int o = 0; o < 8; o++)
                    mma_16816(acc[mi][o], ah[mi], bb[o][0], bb[o][1]);
#pragma unroll
            for (int mi = 0; mi < 2; mi++)
#pragma unroll
                for (int o = 0; o < 8; o++)
                    mma_16816(acc[mi][o], al[mi], bb[o][0], bb[o][1]);
#pragma unroll
            for (int g4 = 0; g4 < 4; g4++) {          // B lo frags
                uint32_t off = (uint32_t)((kk + (g >> 1) * 8 + (lane & 7)) * 136
                                          + wn * 64 + g4 * 16 + (g & 1) * 8) * 2;
                uint32_t r4[4];
                ldm_x4_t(r4, bBl + off);
                bb[g4 * 2 + 0][0] = r4[0]; bb[g4 * 2 + 0][1] = r4[2];
                bb[g4 * 2 + 1][0] = r4[1]; bb[g4 * 2 + 1][1] = r4[3];
            }
#pragma unroll
            for (int mi = 0; mi < 2; mi++)
#pragma unroll
                for (int o = 0; o < 8; o++)
                    mma_16816(acc[mi][o], ah[mi], bb[o][0], bb[o][1]);
        }
        __syncthreads();
    }
#pragma unroll
    for (int mi = 0; mi < 2; mi++)
#pragma unroll
        for (int o = 0; o < 8; o++)
#pragma unroll
            for (int half = 0; half < 2; half++) {
                int row = m0 + wm * 32 + mi * 16 + (lane >> 2) + half * 8;
                int col = n0 + wn * 64 + o * 8 + (lane & 3) * 2;
                float2 w;
                w.x = acc[mi][o][half * 2 + 0];
                w.y = acc[mi][o][half * 2 + 1];
                *(float2*)&C[(size_t)row * 1024 + col] = w;
            }
}

// K1: q/k/v projections (tensor, split-bf16)
__global__ void __launch_bounds__(256, 2)
proj_mma_kernel(const float* __restrict__ x, const float* __restrict__ Wq,
                const float* __restrict__ Wk, const float* __restrict__ Wv)
{
    const float* B = (blockIdx.z == 0) ? Wq : (blockIdx.z == 1 ? Wk : Wv);
    gemm_split(x, B, &g_lin[blockIdx.z][0][0]);
}

// K6: out = g_o @ Wo (tensor, split-bf16)
__global__ void __launch_bounds__(256, 2)
out_mma_kernel(const float* __restrict__ Wo, float* __restrict__ out)
{
    gemm_split(&g_o[0][0], Wo, out);
}

// K2: depthwise conv; Q,K as bf16, V fp32
__global__ void conv_kernel(const float* __restrict__ cq,
                            const float* __restrict__ ck,
                            const float* __restrict__ cv)
{
    int idx = blockIdx.x * 256 + threadIdx.x;
    int z   = idx / (NW * NBINS);
    int rem = idx - z * (NW * NBINS);
    int w   = rem >> 10;
    int c   = rem & 1023;
    const float* cw = (z == 0) ? cq : (z == 1 ? ck : cv);
    float w0 = cw[c * 3 + 0], w1 = cw[c * 3 + 1], w2 = cw[c * 3 + 2];
    float acc = g_lin[z][w][c] * w1;
    if (w > 0)      acc += g_lin[z][w - 1][c] * w0;
    if (w < NW - 1) acc += g_lin[z][w + 1][c] * w2;
    if (z == 0)      g_qb[w][c] = __float2bfloat16(acc);
    else if (z == 1) g_kb[w][c] = __float2bfloat16(acc);
    else             g_v[w][c]  = acc;
}

// K2b: relw transpose + bf16 convert
__global__ void relw_cvt_kernel(const float* __restrict__ relw)
{
    int idx = blockIdx.x * 256 + threadIdx.x;   // 64*2048
    int d = idx >> 11, i = idx & 2047;
    g_rwb[i][d] = __float2bfloat16(relw[idx]);
}

// K2c: V -> per-head transposed hi/lo bf16 (tiled 64x64 transpose)
__global__ void __launch_bounds__(256)
vt_split_kernel()
{
    __shared__ float tile[64][65];
    const int w0 = blockIdx.x * 64, h = blockIdx.y;
    const int t = threadIdx.x;
#pragma unroll
    for (int s = 0; s < 4; s++) {
        int e = t + 256 * s;
        int r = e >> 4, c4 = e & 15;
        float4 v = *(const float4*)&g_v[w0 + r][h * 64 + c4 * 4];
        tile[r][c4 * 4 + 0] = v.x; tile[r][c4 * 4 + 1] = v.y;
        tile[r][c4 * 4 + 2] = v.z; tile[r][c4 * 4 + 3] = v.w;
    }
    __syncthreads();
#pragma unroll
    for (int s = 0; s < 4; s++) {
        int e = t + 256 * s;
        int d = e >> 4, w4 = e & 15;
        __nv_bfloat16 hh[4], ll[4];
#pragma unroll
        for (int i = 0; i < 4; i++) {
            float f = tile[w4 * 4 + i][d];
            hh[i] = __float2bfloat16(f);
            ll[i] = __float2bfloat16(f - __bfloat162float(hh[i]));
        }
        *(uint2*)&g_vth[h][d][w0 + w4 * 4] = *(uint2*)hh;
        *(uint2*)&g_vtl[h][d][w0 + w4 * 4] = *(uint2*)ll;
    }
}

// K3: qk via mma.sync bf16 (R4/R5 version — best known)
#define QK_RS 72
__global__ void __launch_bounds__(256)
qk_mma_kernel(const float* __restrict__ prev, float* __restrict__ qk)
{
    extern __shared__ __nv_bfloat16 smb[];
    __nv_bfloat16* sQi = smb;
    __nv_bfloat16* sKj = smb + 128 * QK_RS;
    __nv_bfloat16* sQj = smb + 2 * 128 * QK_RS;
    __nv_bfloat16* sRw = smb + 3 * 128 * QK_RS;

    const int t = threadIdx.x, wid = t >> 5, lane = t & 31;
    const int j0 = blockIdx.x * 128, i0 = blockIdx.y * 128, h = blockIdx.z;

    {
        const int r = t & 127;
        const int ch0 = (t >> 7) * 4;
        const uint4* qi = (const uint4*)&g_qb[i0 + r][h * 64];
        const uint4* kj = (const uint4*)&g_kb[j0 + r][h * 64];
        const uint4* qj = (const uint4*)&g_qb[j0 + r][h * 64];
        const uint4* rw = (const uint4*)&g_rwb[i0 + r][0];
#pragma unroll
        for (int c = 0; c < 4; c++) {
            int c16 = ch0 + c;
            *(uint4*)((char*)sQi + r * 144 + c16 * 16) = qi[c16];
            *(uint4*)((char*)sKj + r * 144 + c16 * 16) = kj[c16];
            *(uint4*)((char*)sQj + r * 144 + c16 * 16) = qj[c16];
            *(uint4*)((char*)sRw + r * 144 + c16 * 16) = rw[c16];
        }
    }
    __syncthreads();

    const int wm = wid & 1;
    const int wn = wid >> 1;
    const uint32_t sbQi = smem_u32(sQi), sbKj = smem_u32(sKj);
    const uint32_t sbQj = smem_u32(sQj), sbRw = smem_u32(sRw);

    float c[4][4][4];
#pragma unroll
    for (int mi = 0; mi < 4; mi++)
#pragma unroll
        for (int ni = 0; ni < 4; ni++)
#pragma unroll
            for (int e = 0; e < 4; e++) c[mi][ni][e] = 0.f;

#pragma unroll
    for (int term = 0; term < 2; term++) {
        const uint32_t sbA = term ? sbRw : sbQi;
        const uint32_t sbB = term ? sbQj : sbKj;
#pragma unroll
        for (int ks = 0; ks < 4; ks++) {
            const int kcol = ks * 16 + (lane >> 4) * 8;
            uint32_t a[4][4];
#pragma unroll
            for (int mi = 0; mi < 4; mi++) {
                int row = wm * 64 + mi * 16 + (lane & 15);
                ldm_x4(a[mi], sbA + (uint32_t)(row * 144 + kcol * 2));
            }
            uint32_t b[4][2];
#pragma unroll
            for (int nh = 0; nh < 2; nh++) {
                int row = wn * 32 + nh * 16 + (lane & 15);
                uint32_t r4[4];
                ldm_x4(r4, sbB + (uint32_t)(row * 144 + kcol * 2));
                b[nh * 2 + 0][0] = r4[0]; b[nh * 2 + 0][1] = r4[2];
                b[nh * 2 + 1][0] = r4[1]; b[nh * 2 + 1][1] = r4[3];
            }
#pragma unroll
            for (int mi = 0; mi < 4; mi++)
#pragma unroll
                for (int ni = 0; ni < 4; ni++)
                    mma_16816(c[mi][ni], a[mi], b[ni][0], b[ni][1]);
        }
    }

    const float inv = 1.0f / 32.0f;
    const int qr = lane >> 2, qc = (lane & 3) * 2;
#pragma unroll
    for (int mi = 0; mi < 4; mi++) {
#pragma unroll
        for (int ni = 0; ni < 4; ni++) {
#pragma unroll
            for (int half = 0; half < 2; half++) {
                int row = i0 + wm * 64 + mi * 16 + qr + half * 8;
                int col = j0 + wn * 32 + ni * 8 + qc;
                size_t off = ((size_t)(h * 2048) + row) * 2048 + col;
                float2 p = *(const float2*)&prev[off];
                float2 o;
                o.x = c[mi][ni][half * 2 + 0] * inv + p.x;
                o.y = c[mi][ni][half * 2 + 1] * inv + p.y;
                *(float2*)&qk[off] = o;
            }
        }
    }
}

// K5: AV via split-bf16 mma, with in-kernel softmax row sums (no max needed:
// |qk| <~ 1 so exp never overflows; softmax is shift-invariant so result is
// identical to the max-subtracted reference).
// Warp w loads P rows w+8s (all 32 lanes on one row) -> per-thread partial
// sums rs[16], one warp shfl-reduction at the end -> smem -> epilogue divide.
#define AV_SMEM 104960
__global__ void __launch_bounds__(256, 2)
av_mma_kernel(const float* __restrict__ qk)
{
    extern __shared__ __nv_bfloat16 avs[];
    __nv_bfloat16* sPh = avs;                       // [128][136]
    __nv_bfloat16* sPl = avs + 128 * 136;
    __nv_bfloat16* sVh = avs + 2 * 128 * 136;       // [64][136]
    __nv_bfloat16* sVl = avs + 2 * 128 * 136 + 64 * 136;
    float* srs = (float*)(avs + 2 * 128 * 136 + 2 * 64 * 136);  // [128]
    const int i0 = blockIdx.x * 128, h = blockIdx.y;
    const int t = threadIdx.x, wid = t >> 5, lane = t & 31;
    const int wm = wid >> 1, wn = wid & 1;          // warp tile 32(m) x 32(n)

    float acc[2][4][4];
#pragma unroll
    for (int mi = 0; mi < 2; mi++)
#pragma unroll
        for (int o = 0; o < 4; o++)
#pragma unroll
            for (int e = 0; e < 4; e++) acc[mi][o][e] = 0.f;
    float rs[16];
#pragma unroll
    for (int s = 0; s < 16; s++) rs[s] = 0.f;

    for (int jb = 0; jb < 16; jb++) {
        const int j0 = jb * 128;
#pragma unroll
        for (int s = 0; s < 16; s++) {              // P = exp(qk), split
            int e = t + 256 * s;
            int r = e >> 5, c4 = e & 31;            // r == wid + 8*s, c4 == lane
            size_t off = ((size_t)(h * 2048 + i0 + r)) * 2048 + j0 + c4 * 4;
            float4 x = *(const float4*)&qk[off];
            float4 p;
            p.x = __expf(x.x); p.y = __expf(x.y);
            p.z = __expf(x.z); p.w = __expf(x.w);
            rs[s] += p.x + p.y + p.z + p.w;
            split_store(p, &sPh[r * 136 + c4 * 4], &sPl[r * 136 + c4 * 4]);
        }
#pragma unroll
        for (int s = 0; s < 8; s++) {               // V^T tiles hi/lo
            int e = t + 256 * s;
            int d = e >> 5, c4 = e & 31;
            *(uint2*)&sVh[d * 136 + c4 * 4] = *(const uint2*)&g_vth[h][d][j0 + c4 * 4];
            *(uint2*)&sVl[d * 136 + c4 * 4] = *(const uint2*)&g_vtl[h][d][j0 + c4 * 4];
        }
        __syncthreads();
        const uint32_t bPh = smem_u32(sPh), bPl = smem_u32(sPl);
        const uint32_t bVh = smem_u32(sVh), bVl = smem_u32(sVl);
#pragma unroll
        for (int kk = 0; kk < 128; kk += 16) {
            uint32_t ah[2][4], al[2][4], bv[4][2];
#pragma unroll
            for (int mi = 0; mi < 2; mi++) {
                uint32_t off = (uint32_t)((wm * 32 + mi * 16 + (lane & 15)) * 136
                                          + kk + (lane >> 4) * 8) * 2;
                ldm_x4(ah[mi], bPh + off);
                ldm_x4(al[mi], bPl + off);
            }
#pragma unroll
            for (int nb = 0; nb < 2; nb++) {        // Vh frags
                uint32_t off = (uint32_t)((wn * 32 + nb * 16 + (lane & 15)) * 136
                                          + kk + (lane >> 4) * 8) * 2;
                uint32_t r4[4];
                ldm_x4(r4, bVh + off);
                bv[nb * 2 + 0][0] = r4[0]; bv[nb * 2 + 0][1] = r4[2];
                bv[nb * 2 + 1][0] = r4[1]; bv[nb * 2 + 1][1] = r4[3];
            }
#pragma unroll
            for (int mi = 0; mi < 2; mi++)
#pragma unroll
                for (int o = 0; o < 4; o++) {
                    mma_16816(acc[mi][o], ah[mi], bv[o][0], bv[o][1]);
                    mma_16816(acc[mi][o], al[mi], bv[o][0], bv[o][1]);
                }
#pragma unroll
            for (int nb = 0; nb < 2; nb++) {        // Vl frags
                uint32_t off = (uint32_t)((wn * 32 + nb * 16 + (lane & 15)) * 136
                                          + kk + (lane >> 4) * 8) * 2;
                uint32_t r4[4];
                ldm_x4(r4, bVl + off);
                bv[nb * 2 + 0][0] = r4[0]; bv[nb * 2 + 0][1] = r4[2];
                bv[nb * 2 + 1][0] = r4[1]; bv[nb * 2 + 1][1] = r4[3];
            }
#pragma unroll
            for (int mi = 0; mi < 2; mi++)
#pragma unroll
                for (int o = 0; o < 4; o++)
                    mma_16816(acc[mi][o], ah[mi], bv[o][0], bv[o][1]);
        }
        __syncthreads();
    }

    // warp-reduce row sums: warp wid owns rows wid + 8*s
#pragma unroll
    for (int s = 0; s < 16; s++) {
        float v = rs[s];
#pragma unroll
        for (int o = 16; o > 0; o >>= 1)
            v += __shfl_xor_sync(0xffffffffu, v, o);
        if (lane == 0) srs[wid + 8 * s] = v;
    }
    __syncthreads();

#pragma unroll
    for (int mi = 0; mi < 2; mi++)
#pragma unroll
        for (int o = 0; o < 4; o++)
#pragma unroll
            for (int half = 0; half < 2; half++) {
                int lrow = wm * 32 + mi * 16 + (lane >> 2) + half * 8;
                float invl = 1.0f / srs[lrow];
                int col = h * 64 + wn * 32 + o * 8 + (lane & 3) * 2;
                float2 w;
                w.x = acc[mi][o][half * 2 + 0] * invl;
                w.y = acc[mi][o][half * 2 + 1] * invl;
                *(float2*)&g_o[i0 + lrow][col] = w;
            }
}

// --------------------------------------------------------------------------
extern "C" void kernel_launch(void* const* d_in, const int* in_sizes, int n_in,
                              void* d_out, int out_size)
{
    const float* x    = (const float*)d_in[0];
    const float* prev = (const float*)d_in[1];
    const float* Wq   = (const float*)d_in[2];
    const float* Wk   = (const float*)d_in[3];
    const float* Wv   = (const float*)d_in[4];
    const float* Wo   = (const float*)d_in[5];
    const float* cq   = (const float*)d_in[6];
    const float* ck   = (const float*)d_in[7];
    const float* cv   = (const float*)d_in[8];
    const float* relw = (const float*)d_in[9];

    float* out = (float*)d_out;                 // (1,2048,1024)
    float* qk  = out + (size_t)NW * NBINS;      // (1,16,2048,2048)

    const size_t QK_SMEM = (size_t)4 * 128 * QK_RS * sizeof(__nv_bfloat16); // 73728
    cudaFuncSetAttribute(proj_mma_kernel, cudaFuncAttributeMaxDynamicSharedMemorySize, GS_SMEM);
    cudaFuncSetAttribute(out_mma_kernel,  cudaFuncAttributeMaxDynamicSharedMemorySize, GS_SMEM);
    cudaFuncSetAttribute(qk_mma_kernel,   cudaFuncAttributeMaxDynamicSharedMemorySize, (int)QK_SMEM);
    cudaFuncSetAttribute(av_mma_kernel,   cudaFuncAttributeMaxDynamicSharedMemorySize, AV_SMEM);

    proj_mma_kernel<<<dim3(8, 16, 3), 256, GS_SMEM>>>(x, Wq, Wk, Wv);
    conv_kernel<<<(3 * NW * NBINS) / 256, 256>>>(cq, ck, cv);
    relw_cvt_kernel<<<(HD * NW) / 256, 256>>>(relw);
    vt_split_kernel<<<dim3(32, 16), 256>>>();
    qk_mma_kernel<<<dim3(16, 16, 16), 256, QK_SMEM>>>(prev, qk);
    av_mma_kernel<<<dim3(16, 16), 256, AV_SMEM>>>(qk);
    out_mma_kernel<<<dim3(8, 16), 256, GS_SMEM>>>(Wo, out);
}

// round 8
// speedup vs baseline: 1.3736x; 1.0854x over previous
#include <cuda_runtime.h>
#include <cuda_bf16.h>
#include <math.h>
#include <stdint.h>

#define NW    2048
#define NBINS 1024
#define NH    16
#define HD    64

// ---------------- scratch (device globals: allocation-free) ----------------
__device__ float g_lin[3][NW][NBINS];          // post-projection q/k/v (pre-conv)
__device__ float g_v[NW][NBINS];               // post-conv V fp32
__device__ __nv_bfloat16 g_qb[NW][NBINS];      // post-conv Q, bf16
__device__ __nv_bfloat16 g_kb[NW][NBINS];      // post-conv K, bf16
__device__ __nv_bfloat16 g_rwb[NW][HD];        // relw^T bf16
__device__ __nv_bfloat16 g_vth[NH][HD][NW];    // V^T per head, hi part
__device__ __nv_bfloat16 g_vtl[NH][HD][NW];    // V^T per head, lo part
__device__ float g_m[NH * NW];                 // softmax row max
__device__ float g_l[NH * NW];                 // softmax row sum
__device__ float g_o[NW][NBINS];               // attention output (pre-Wo)

// ======================= PTX helpers (generic sm_80+) ======================
__device__ __forceinline__ uint32_t smem_u32(const void* p) {
    uint32_t a;
    asm("{ .reg .u64 t; cvta.to.shared.u64 t, %1; cvt.u32.u64 %0, t; }"
        : "=r"(a) : "l"(p));
    return a;
}
__device__ __forceinline__ void ldm_x4(uint32_t r[4], uint32_t addr) {
    asm volatile("ldmatrix.sync.aligned.m8n8.x4.shared.b16 {%0,%1,%2,%3}, [%4];"
                 : "=r"(r[0]), "=r"(r[1]), "=r"(r[2]), "=r"(r[3]) : "r"(addr));
}
__device__ __forceinline__ void ldm_x4_t(uint32_t r[4], uint32_t addr) {
    asm volatile("ldmatrix.sync.aligned.m8n8.x4.trans.shared.b16 {%0,%1,%2,%3}, [%4];"
                 : "=r"(r[0]), "=r"(r[1]), "=r"(r[2]), "=r"(r[3]) : "r"(addr));
}
__device__ __forceinline__ void mma_16816(float c[4], const uint32_t a[4],
                                          uint32_t b0, uint32_t b1) {
    asm volatile(
        "mma.sync.aligned.m16n8k16.row.col.f32.bf16.bf16.f32 "
        "{%0,%1,%2,%3}, {%4,%5,%6,%7}, {%8,%9}, {%0,%1,%2,%3};"
        : "+f"(c[0]), "+f"(c[1]), "+f"(c[2]), "+f"(c[3])
        : "r"(a[0]), "r"(a[1]), "r"(a[2]), "r"(a[3]), "r"(b0), "r"(b1));
}
// split a float4 into hi/lo bf16 quads and store (8B each)
__device__ __forceinline__ void split_store(float4 v, __nv_bfloat16* ph,
                                            __nv_bfloat16* pl) {
    __nv_bfloat16 hh[4], ll[4];
#pragma unroll
    for (int i = 0; i < 4; i++) {
        float f = (&v.x)[i];
        hh[i] = __float2bfloat16(f);
        ll[i] = __float2bfloat16(f - __bfloat162float(hh[i]));
    }
    *(uint2*)ph = *(uint2*)hh;
    *(uint2*)pl = *(uint2*)ll;
}

// ================= split-bf16 tensor GEMM: C = A(2048x1024) @ B(1024x1024) ==
#define GS_SMEM 71680
__device__ __forceinline__ void gemm_split(const float* __restrict__ A,
                                           const float* __restrict__ B,
                                           float* __restrict__ C)
{
    extern __shared__ __nv_bfloat16 gs[];
    __nv_bfloat16* sAh = gs;                // [128][72]
    __nv_bfloat16* sAl = gs + 9216;
    __nv_bfloat16* sBh = gs + 18432;        // [64][136]  (k-major)
    __nv_bfloat16* sBl = gs + 27136;
    const int t = threadIdx.x, wid = t >> 5, lane = t & 31;
    const int m0 = blockIdx.y * 128, n0 = blockIdx.x * 128;
    const int wm = wid >> 1, wn = wid & 1;  // warp tile 32(m) x 64(n)

    float acc[2][8][4];
#pragma unroll
    for (int mi = 0; mi < 2; mi++)
#pragma unroll
        for (int o = 0; o < 8; o++)
#pragma unroll
            for (int e = 0; e < 4; e++) acc[mi][o][e] = 0.f;

    for (int k0 = 0; k0 < 1024; k0 += 64) {
#pragma unroll
        for (int s = 0; s < 8; s++) {                 // A 128x64
            int e = t + 256 * s;
            int r = e >> 4, c4 = e & 15;
            float4 a = *(const float4*)&A[(size_t)(m0 + r) * 1024 + k0 + c4 * 4];
            split_store(a, &sAh[r * 72 + c4 * 4], &sAl[r * 72 + c4 * 4]);
        }
#pragma unroll
        for (int s = 0; s < 8; s++) {                 // B 64x128
            int e = t + 256 * s;
            int kr = e >> 5, c4 = e & 31;
            float4 b = *(const float4*)&B[(size_t)(k0 + kr) * 1024 + n0 + c4 * 4];
            split_store(b, &sBh[kr * 136 + c4 * 4], &sBl[kr * 136 + c4 * 4]);
        }
        __syncthreads();
        const uint32_t bAh = smem_u32(sAh), bAl = smem_u32(sAl);
        const uint32_t bBh = smem_u32(sBh), bBl = smem_u32(sBl);
        const int g = lane >> 3;
#pragma unroll
        for (int kk = 0; kk < 64; kk += 16) {
            uint32_t ah[2][4], al[2][4], bb[8][2];
#pragma unroll
            for (int mi = 0; mi < 2; mi++) {
                uint32_t off = (uint32_t)((wm * 32 + mi * 16 + (lane & 15)) * 72
                                          + kk + (lane >> 4) * 8) * 2;
                ldm_x4(ah[mi], bAh + off);
                ldm_x4(al[mi], bAl + off);
            }
#pragma unroll
            for (int g4 = 0; g4 < 4; g4++) {          // B hi frags via trans
                uint32_t off = (uint32_t)((kk + (g >> 1) * 8 + (lane & 7)) * 136
                                          + wn * 64 + g4 * 16 + (g & 1) * 8) * 2;
                uint32_t r4[4];
                ldm_x4_t(r4, bBh + off);
                bb[g4 * 2 + 0][0] = r4[0]; bb[g4 * 2 + 0][1] = r4[2];
                bb[g4 * 2 + 1][0] = r4[1]; bb[g4 * 2 + 1][1] = r4[3];
            }
#pragma unroll
            for (int mi = 0; mi < 2; mi++)
#pragma unroll
                for (int o = 0; o < 8; o++)
                    mma_16816(acc[mi][o], ah[mi], bb[o][0], bb[o][1]);
#pragma unroll
            for (int mi = 0; mi < 2; mi++)
#pragma unroll
                for (int o = 0; o < 8; o++)
                    mma_16816(acc[mi][o], al[mi], bb[o][0], bb[o][1]);
#pragma unroll
            for (int g4 = 0; g4 < 4; g4++) {          // B lo frags
                uint32_t off = (uint32_t)((kk + (g >> 1) * 8 + (lane & 7)) * 136
                                          + wn * 64 + g4 * 16 + (g & 1) * 8) * 2;
                uint32_t r4[4];
                ldm_x4_t(r4, bBl + off);
                bb[g4 * 2 + 0][0] = r4[0]; bb[g4 * 2 + 0][1] = r4[2];
                bb[g4 * 2 + 1][0] = r4[1]; bb[g4 * 2 + 1][1] = r4[3];
            }
#pragma unroll
            for (int mi = 0; mi < 2; mi++)
#pragma unroll
                for (int o = 0; o < 8; o++)
                    mma_16816(acc[mi][o], ah[mi], bb[o][0], bb[o][1]);
        }
        __syncthreads();
    }
#pragma unroll
    for (int mi = 0; mi < 2; mi++)
#pragma unroll
        for (int o = 0; o < 8; o++)
#pragma unroll
            for (int half = 0; half < 2; half++) {
                int row = m0 + wm * 32 + mi * 16 + (lane >> 2) + half * 8;
                int col = n0 + wn * 64 + o * 8 + (lane & 3) * 2;
                float2 w;
                w.x = acc[mi][o][half * 2 + 0];
                w.y = acc[mi][o][half * 2 + 1];
                *(float2*)&C[(size_t)row * 1024 + col] = w;
            }
}

// K1: q/k/v projections (tensor, split-bf16)
__global__ void __launch_bounds__(256, 2)
proj_mma_kernel(const float* __restrict__ x, const float* __restrict__ Wq,
                const float* __restrict__ Wk, const float* __restrict__ Wv)
{
    const float* B = (blockIdx.z == 0) ? Wq : (blockIdx.z == 1 ? Wk : Wv);
    gemm_split(x, B, &g_lin[blockIdx.z][0][0]);
}

// K6: out = g_o @ Wo (tensor, split-bf16)
__global__ void __launch_bounds__(256, 2)
out_mma_kernel(const float* __restrict__ Wo, float* __restrict__ out)
{
    gemm_split(&g_o[0][0], Wo, out);
}

// K2: depthwise conv; Q,K as bf16, V fp32
__global__ void conv_kernel(const float* __restrict__ cq,
                            const float* __restrict__ ck,
                            const float* __restrict__ cv)
{
    int idx = blockIdx.x * 256 + threadIdx.x;
    int z   = idx / (NW * NBINS);
    int rem = idx - z * (NW * NBINS);
    int w   = rem >> 10;
    int c   = rem & 1023;
    const float* cw = (z == 0) ? cq : (z == 1 ? ck : cv);
    float w0 = cw[c * 3 + 0], w1 = cw[c * 3 + 1], w2 = cw[c * 3 + 2];
    float acc = g_lin[z][w][c] * w1;
    if (w > 0)      acc += g_lin[z][w - 1][c] * w0;
    if (w < NW - 1) acc += g_lin[z][w + 1][c] * w2;
    if (z == 0)      g_qb[w][c] = __float2bfloat16(acc);
    else if (z == 1) g_kb[w][c] = __float2bfloat16(acc);
    else             g_v[w][c]  = acc;
}

// K2b: relw transpose + bf16 convert
__global__ void relw_cvt_kernel(const float* __restrict__ relw)
{
    int idx = blockIdx.x * 256 + threadIdx.x;   // 64*2048
    int d = idx >> 11, i = idx & 2047;
    g_rwb[i][d] = __float2bfloat16(relw[idx]);
}

// K2c: V -> per-head transposed hi/lo bf16 (tiled 64x64 transpose)
__global__ void __launch_bounds__(256)
vt_split_kernel()
{
    __shared__ float tile[64][65];
    const int w0 = blockIdx.x * 64, h = blockIdx.y;
    const int t = threadIdx.x;
#pragma unroll
    for (int s = 0; s < 4; s++) {
        int e = t + 256 * s;
        int r = e >> 4, c4 = e & 15;
        float4 v = *(const float4*)&g_v[w0 + r][h * 64 + c4 * 4];
        tile[r][c4 * 4 + 0] = v.x; tile[r][c4 * 4 + 1] = v.y;
        tile[r][c4 * 4 + 2] = v.z; tile[r][c4 * 4 + 3] = v.w;
    }
    __syncthreads();
#pragma unroll
    for (int s = 0; s < 4; s++) {
        int e = t + 256 * s;
        int d = e >> 4, w4 = e & 15;
        __nv_bfloat16 hh[4], ll[4];
#pragma unroll
        for (int i = 0; i < 4; i++) {
            float f = tile[w4 * 4 + i][d];
            hh[i] = __float2bfloat16(f);
            ll[i] = __float2bfloat16(f - __bfloat162float(hh[i]));
        }
        *(uint2*)&g_vth[h][d][w0 + w4 * 4] = *(uint2*)hh;
        *(uint2*)&g_vtl[h][d][w0 + w4 * 4] = *(uint2*)ll;
    }
}

// K3: qk via mma.sync bf16. Epilogue staged through smem so prev-read and
// qk-write are fully coalesced float4 rows (R4 epilogue touched 8 lines per
// warp store; this touches 2).
#define QK_RS 72
__global__ void __launch_bounds__(256)
qk_mma_kernel(const float* __restrict__ prev, float* __restrict__ qk)
{
    extern __shared__ __nv_bfloat16 smb[];
    __nv_bfloat16* sQi = smb;
    __nv_bfloat16* sKj = smb + 128 * QK_RS;
    __nv_bfloat16* sQj = smb + 2 * 128 * QK_RS;
    __nv_bfloat16* sRw = smb + 3 * 128 * QK_RS;

    const int t = threadIdx.x, wid = t >> 5, lane = t & 31;
    const int j0 = blockIdx.x * 128, i0 = blockIdx.y * 128, h = blockIdx.z;

    {
        const int r = t & 127;
        const int ch0 = (t >> 7) * 4;
        const uint4* qi = (const uint4*)&g_qb[i0 + r][h * 64];
        const uint4* kj = (const uint4*)&g_kb[j0 + r][h * 64];
        const uint4* qj = (const uint4*)&g_qb[j0 + r][h * 64];
        const uint4* rw = (const uint4*)&g_rwb[i0 + r][0];
#pragma unroll
        for (int c = 0; c < 4; c++) {
            int c16 = ch0 + c;
            *(uint4*)((char*)sQi + r * 144 + c16 * 16) = qi[c16];
            *(uint4*)((char*)sKj + r * 144 + c16 * 16) = kj[c16];
            *(uint4*)((char*)sQj + r * 144 + c16 * 16) = qj[c16];
            *(uint4*)((char*)sRw + r * 144 + c16 * 16) = rw[c16];
        }
    }
    __syncthreads();

    const int wm = wid & 1;
    const int wn = wid >> 1;
    const uint32_t sbQi = smem_u32(sQi), sbKj = smem_u32(sKj);
    const uint32_t sbQj = smem_u32(sQj), sbRw = smem_u32(sRw);

    float c[4][4][4];
#pragma unroll
    for (int mi = 0; mi < 4; mi++)
#pragma unroll
        for (int ni = 0; ni < 4; ni++)
#pragma unroll
            for (int e = 0; e < 4; e++) c[mi][ni][e] = 0.f;

#pragma unroll
    for (int term = 0; term < 2; term++) {
        const uint32_t sbA = term ? sbRw : sbQi;
        const uint32_t sbB = term ? sbQj : sbKj;
#pragma unroll
        for (int ks = 0; ks < 4; ks++) {
            const int kcol = ks * 16 + (lane >> 4) * 8;
            uint32_t a[4][4];
#pragma unroll
            for (int mi = 0; mi < 4; mi++) {
                int row = wm * 64 + mi * 16 + (lane & 15);
                ldm_x4(a[mi], sbA + (uint32_t)(row * 144 + kcol * 2));
            }
            uint32_t b[4][2];
#pragma unroll
            for (int nh = 0; nh < 2; nh++) {
                int row = wn * 32 + nh * 16 + (lane & 15);
                uint32_t r4[4];
                ldm_x4(r4, sbB + (uint32_t)(row * 144 + kcol * 2));
                b[nh * 2 + 0][0] = r4[0]; b[nh * 2 + 0][1] = r4[2];
                b[nh * 2 + 1][0] = r4[1]; b[nh * 2 + 1][1] = r4[3];
            }
#pragma unroll
            for (int mi = 0; mi < 4; mi++)
#pragma unroll
                for (int ni = 0; ni < 4; ni++)
                    mma_16816(c[mi][ni], a[mi], b[ni][0], b[ni][1]);
        }
    }

    // ---- staged epilogue: accumulators -> smem (fragment layout) ----
    __syncthreads();                       // operand tiles are dead; reuse smem
    float* sC = (float*)smb;               // [128][132] (row stride 16B-aligned)
    const float inv = 1.0f / 32.0f;
    const int qr = lane >> 2, qc = (lane & 3) * 2;
#pragma unroll
    for (int mi = 0; mi < 4; mi++)
#pragma unroll
        for (int ni = 0; ni < 4; ni++)
#pragma unroll
            for (int half = 0; half < 2; half++) {
                int row = wm * 64 + mi * 16 + qr + half * 8;
                int col = wn * 32 + ni * 8 + qc;
                float2 w;
                w.x = c[mi][ni][half * 2 + 0] * inv;
                w.y = c[mi][ni][half * 2 + 1] * inv;
                *(float2*)&sC[row * 132 + col] = w;
            }
    __syncthreads();

    // ---- coalesced prev-read + add + qk-write: float4 over full rows ----
    const size_t base = ((size_t)(h * 2048 + i0)) * 2048 + j0;
#pragma unroll
    for (int s = 0; s < 16; s++) {
        int e = t + 256 * s;
        int r = e >> 5, c4 = e & 31;
        size_t off = base + (size_t)r * 2048 + c4 * 4;
        float4 p = *(const float4*)&prev[off];
        float4 v = *(const float4*)&sC[r * 132 + c4 * 4];
        float4 o;
        o.x = v.x + p.x; o.y = v.y + p.y; o.z = v.z + p.z; o.w = v.w + p.w;
        *(float4*)&qk[off] = o;
    }
}

// K4: per-row softmax stats
__global__ void __launch_bounds__(256)
rowstat_kernel(const float* __restrict__ qk)
{
    const int row = blockIdx.x;
    const float* p = qk + (size_t)row * 2048;
    const int t = threadIdx.x;
    float v[8];
    float m = -1e30f;
#pragma unroll
    for (int s = 0; s < 8; s++) { v[s] = p[t + 256 * s]; m = fmaxf(m, v[s]); }
#pragma unroll
    for (int o = 16; o > 0; o >>= 1)
        m = fmaxf(m, __shfl_xor_sync(0xffffffffu, m, o));

    __shared__ float redm[8], reds[8];
    const int w = t >> 5, lane = t & 31;
    if (lane == 0) redm[w] = m;
    __syncthreads();
    float bm = fmaxf(fmaxf(fmaxf(redm[0], redm[1]), fmaxf(redm[2], redm[3])),
                     fmaxf(fmaxf(redm[4], redm[5]), fmaxf(redm[6], redm[7])));
    float sum = 0.f;
#pragma unroll
    for (int s = 0; s < 8; s++) sum += __expf(v[s] - bm);
#pragma unroll
    for (int o = 16; o > 0; o >>= 1)
        sum += __shfl_xor_sync(0xffffffffu, sum, o);
    if (lane == 0) reds[w] = sum;
    __syncthreads();
    if (t == 0) {
        g_m[row] = bm;
        g_l[row] = reds[0] + reds[1] + reds[2] + reds[3] +
                   reds[4] + reds[5] + reds[6] + reds[7];
    }
}

// K5: AV via split-bf16 mma (R5 version)
#define AV_SMEM 104448
__global__ void __launch_bounds__(256, 2)
av_mma_kernel(const float* __restrict__ qk)
{
    extern __shared__ __nv_bfloat16 avs[];
    __nv_bfloat16* sPh = avs;                       // [128][136]
    __nv_bfloat16* sPl = avs + 128 * 136;
    __nv_bfloat16* sVh = avs + 2 * 128 * 136;       // [64][136]
    __nv_bfloat16* sVl = avs + 2 * 128 * 136 + 64 * 136;
    const int i0 = blockIdx.x * 128, h = blockIdx.y;
    const int t = threadIdx.x, wid = t >> 5, lane = t & 31;
    const int wm = wid >> 1, wn = wid & 1;          // warp tile 32(m) x 32(n)

    float acc[2][4][4];
#pragma unroll
    for (int mi = 0; mi < 2; mi++)
#pragma unroll
        for (int o = 0; o < 4; o++)
#pragma unroll
            for (int e = 0; e < 4; e++) acc[mi][o][e] = 0.f;

    for (int jb = 0; jb < 16; jb++) {
        const int j0 = jb * 128;
#pragma unroll
        for (int s = 0; s < 16; s++) {              // P = exp(qk - m), split
            int e = t + 256 * s;
            int r = e >> 5, c4 = e & 31;
            size_t off = ((size_t)(h * 2048 + i0 + r)) * 2048 + j0 + c4 * 4;
            float4 x = *(const float4*)&qk[off];
            float mrow = g_m[h * 2048 + i0 + r];
            float4 p;
            p.x = __expf(x.x - mrow); p.y = __expf(x.y - mrow);
            p.z = __expf(x.z - mrow); p.w = __expf(x.w - mrow);
            split_store(p, &sPh[r * 136 + c4 * 4], &sPl[r * 136 + c4 * 4]);
        }
#pragma unroll
        for (int s = 0; s < 8; s++) {               // V^T tiles hi/lo
            int e = t + 256 * s;
            int d = e >> 5, c4 = e & 31;
            *(uint2*)&sVh[d * 136 + c4 * 4] = *(const uint2*)&g_vth[h][d][j0 + c4 * 4];
            *(uint2*)&sVl[d * 136 + c4 * 4] = *(const uint2*)&g_vtl[h][d][j0 + c4 * 4];
        }
        __syncthreads();
        const uint32_t bPh = smem_u32(sPh), bPl = smem_u32(sPl);
        const uint32_t bVh = smem_u32(sVh), bVl = smem_u32(sVl);
#pragma unroll
        for (int kk = 0; kk < 128; kk += 16) {
            uint32_t ah[2][4], al[2][4], bv[4][2];
#pragma unroll
            for (int mi = 0; mi < 2; mi++) {
                uint32_t off = (uint32_t)((wm * 32 + mi * 16 + (lane & 15)) * 136
                                          + kk + (lane >> 4) * 8) * 2;
                ldm_x4(ah[mi], bPh + off);
                ldm_x4(al[mi], bPl + off);
            }
#pragma unroll
            for (int nb = 0; nb < 2; nb++) {        // Vh frags
                uint32_t off = (uint32_t)((wn * 32 + nb * 16 + (lane & 15)) * 136
                                          + kk + (lane >> 4) * 8) * 2;
                uint32_t r4[4];
                ldm_x4(r4, bVh + off);
                bv[nb * 2 + 0][0] = r4[0]; bv[nb * 2 + 0][1] = r4[2];
                bv[nb * 2 + 1][0] = r4[1]; bv[nb * 2 + 1][1] = r4[3];
            }
#pragma unroll
            for (int mi = 0; mi < 2; mi++)
#pragma unroll
                for (int o = 0; o < 4; o++) {
                    mma_16816(acc[mi][o], ah[mi], bv[o][0], bv[o][1]);
                    mma_16816(acc[mi][o], al[mi], bv[o][0], bv[o][1]);
                }
#pragma unroll
            for (int nb = 0; nb < 2; nb++) {        // Vl frags
                uint32_t off = (uint32_t)((wn * 32 + nb * 16 + (lane & 15)) * 136
                                          + kk + (lane >> 4) * 8) * 2;
                uint32_t r4[4];
                ldm_x4(r4, bVl + off);
                bv[nb * 2 + 0][0] = r4[0]; bv[nb * 2 + 0][1] = r4[2];
                bv[nb * 2 + 1][0] = r4[1]; bv[nb * 2 + 1][1] = r4[3];
            }
#pragma unroll
            for (int mi = 0; mi < 2; mi++)
#pragma unroll
                for (int o = 0; o < 4; o++)
                    mma_16816(acc[mi][o], ah[mi], bv[o][0], bv[o][1]);
        }
        __syncthreads();
    }
#pragma unroll
    for (int mi = 0; mi < 2; mi++)
#pragma unroll
        for (int o = 0; o < 4; o++)
#pragma unroll
            for (int half = 0; half < 2; half++) {
                int row = i0 + wm * 32 + mi * 16 + (lane >> 2) + half * 8;
                float invl = 1.0f / g_l[h * 2048 + row];
                int col = h * 64 + wn * 32 + o * 8 + (lane & 3) * 2;
                float2 w;
                w.x = acc[mi][o][half * 2 + 0] * invl;
                w.y = acc[mi][o][half * 2 + 1] * invl;
                *(float2*)&g_o[row][col] = w;
            }
}

// --------------------------------------------------------------------------
extern "C" void kernel_launch(void* const* d_in, const int* in_sizes, int n_in,
                              void* d_out, int out_size)
{
    const float* x    = (const float*)d_in[0];
    const float* prev = (const float*)d_in[1];
    const float* Wq   = (const float*)d_in[2];
    const float* Wk   = (const float*)d_in[3];
    const float* Wv   = (const float*)d_in[4];
    const float* Wo   = (const float*)d_in[5];
    const float* cq   = (const float*)d_in[6];
    const float* ck   = (const float*)d_in[7];
    const float* cv   = (const float*)d_in[8];
    const float* relw = (const float*)d_in[9];

    float* out = (float*)d_out;                 // (1,2048,1024)
    float* qk  = out + (size_t)NW * NBINS;      // (1,16,2048,2048)

    const size_t QK_SMEM = (size_t)4 * 128 * QK_RS * sizeof(__nv_bfloat16); // 73728
    cudaFuncSetAttribute(proj_mma_kernel, cudaFuncAttributeMaxDynamicSharedMemorySize, GS_SMEM);
    cudaFuncSetAttribute(out_mma_kernel,  cudaFuncAttributeMaxDynamicSharedMemorySize, GS_SMEM);
    cudaFuncSetAttribute(qk_mma_kernel,   cudaFuncAttributeMaxDynamicSharedMemorySize, (int)QK_SMEM);
    cudaFuncSetAttribute(av_mma_kernel,   cudaFuncAttributeMaxDynamicSharedMemorySize, AV_SMEM);

    proj_mma_kernel<<<dim3(8, 16, 3), 256, GS_SMEM>>>(x, Wq, Wk, Wv);
    conv_kernel<<<(3 * NW * NBINS) / 256, 256>>>(cq, ck, cv);
    relw_cvt_kernel<<<(HD * NW) / 256, 256>>>(relw);
    vt_split_kernel<<<dim3(32, 16), 256>>>();
    qk_mma_kernel<<<dim3(16, 16, 16), 256, QK_SMEM>>>(prev, qk);
    rowstat_kernel<<<NH * NW, 256>>>(qk);
    av_mma_kernel<<<dim3(16, 16), 256, AV_SMEM>>>(qk);
    out_mma_kernel<<<dim3(8, 16), 256, GS_SMEM>>>(Wo, out);
}

// round 10
// speedup vs baseline: 1.4160x; 1.0309x over previous
#include <cuda_runtime.h>
#include <cuda_bf16.h>
#include <math.h>
#include <stdint.h>

#define NW    2048
#define NBINS 1024
#define NH    16
#define HD    64

// ---------------- scratch (device globals: allocation-free) ----------------
__device__ float g_lin[3][NW][NBINS];          // post-projection q/k/v (pre-conv)
__device__ float g_v[NW][NBINS];               // post-conv V fp32
__device__ __nv_bfloat16 g_qb[NW][NBINS];      // post-conv Q, bf16
__device__ __nv_bfloat16 g_kb[NW][NBINS];      // post-conv K, bf16
__device__ __nv_bfloat16 g_rwb[NW][HD];        // relw^T bf16
__device__ __nv_bfloat16 g_vth[NH][HD][NW];    // V^T per head, hi part
__device__ __nv_bfloat16 g_vtl[NH][HD][NW];    // V^T per head, lo part
__device__ float g_l[NH * NW];                 // softmax row sum (atomic acc)
__device__ float g_o[NW][NBINS];               // attention output (pre-Wo)

// ======================= PTX helpers (generic sm_80+) ======================
__device__ __forceinline__ uint32_t smem_u32(const void* p) {
    uint32_t a;
    asm("{ .reg .u64 t; cvta.to.shared.u64 t, %1; cvt.u32.u64 %0, t; }"
        : "=r"(a) : "l"(p));
    return a;
}
__device__ __forceinline__ void ldm_x4(uint32_t r[4], uint32_t addr) {
    asm volatile("ldmatrix.sync.aligned.m8n8.x4.shared.b16 {%0,%1,%2,%3}, [%4];"
                 : "=r"(r[0]), "=r"(r[1]), "=r"(r[2]), "=r"(r[3]) : "r"(addr));
}
__device__ __forceinline__ void ldm_x4_t(uint32_t r[4], uint32_t addr) {
    asm volatile("ldmatrix.sync.aligned.m8n8.x4.trans.shared.b16 {%0,%1,%2,%3}, [%4];"
                 : "=r"(r[0]), "=r"(r[1]), "=r"(r[2]), "=r"(r[3]) : "r"(addr));
}
__device__ __forceinline__ void mma_16816(float c[4], const uint32_t a[4],
                                          uint32_t b0, uint32_t b1) {
    asm volatile(
        "mma.sync.aligned.m16n8k16.row.col.f32.bf16.bf16.f32 "
        "{%0,%1,%2,%3}, {%4,%5,%6,%7}, {%8,%9}, {%0,%1,%2,%3};"
        : "+f"(c[0]), "+f"(c[1]), "+f"(c[2]), "+f"(c[3])
        : "r"(a[0]), "r"(a[1]), "r"(a[2]), "r"(a[3]), "r"(b0), "r"(b1));
}
// split a float4 into hi/lo bf16 quads and store (8B each)
__device__ __forceinline__ void split_store(float4 v, __nv_bfloat16* ph,
                                            __nv_bfloat16* pl) {
    __nv_bfloat16 hh[4], ll[4];
#pragma unroll
    for (int i = 0; i < 4; i++) {
        float f = (&v.x)[i];
        hh[i] = __float2bfloat16(f);
        ll[i] = __float2bfloat16(f - __bfloat162float(hh[i]));
    }
    *(uint2*)ph = *(uint2*)hh;
    *(uint2*)pl = *(uint2*)ll;
}
__device__ __forceinline__ void hi_store(float4 v, __nv_bfloat16* ph) {
    __nv_bfloat16 hh[4];
#pragma unroll
    for (int i = 0; i < 4; i++) hh[i] = __float2bfloat16((&v.x)[i]);
    *(uint2*)ph = *(uint2*)hh;
}

// ================= split-bf16 tensor GEMM: C = A(2048x1024) @ B(1024x1024) ==
// full=1: 3-term split (hh + lh + hl). full=0: plain bf16 (hh only).
#define GS_SMEM 71680
__device__ __forceinline__ void gemm_split(const float* __restrict__ A,
                                           const float* __restrict__ B,
                                           float* __restrict__ C,
                                           const bool full)
{
    extern __shared__ __nv_bfloat16 gs[];
    __nv_bfloat16* sAh = gs;                // [128][72]
    __nv_bfloat16* sAl = gs + 9216;
    __nv_bfloat16* sBh = gs + 18432;        // [64][136]  (k-major)
    __nv_bfloat16* sBl = gs + 27136;
    const int t = threadIdx.x, wid = t >> 5, lane = t & 31;
    const int m0 = blockIdx.y * 128, n0 = blockIdx.x * 128;
    const int wm = wid >> 1, wn = wid & 1;  // warp tile 32(m) x 64(n)

    float acc[2][8][4];
#pragma unroll
    for (int mi = 0; mi < 2; mi++)
#pragma unroll
        for (int o = 0; o < 8; o++)
#pragma unroll
            for (int e = 0; e < 4; e++) acc[mi][o][e] = 0.f;

    for (int k0 = 0; k0 < 1024; k0 += 64) {
#pragma unroll
        for (int s = 0; s < 8; s++) {                 // A 128x64
            int e = t + 256 * s;
            int r = e >> 4, c4 = e & 15;
            float4 a = *(const float4*)&A[(size_t)(m0 + r) * 1024 + k0 + c4 * 4];
            if (full) split_store(a, &sAh[r * 72 + c4 * 4], &sAl[r * 72 + c4 * 4]);
            else      hi_store(a, &sAh[r * 72 + c4 * 4]);
        }
#pragma unroll
        for (int s = 0; s < 8; s++) {                 // B 64x128
            int e = t + 256 * s;
            int kr = e >> 5, c4 = e & 31;
            float4 b = *(const float4*)&B[(size_t)(k0 + kr) * 1024 + n0 + c4 * 4];
            if (full) split_store(b, &sBh[kr * 136 + c4 * 4], &sBl[kr * 136 + c4 * 4]);
            else      hi_store(b, &sBh[kr * 136 + c4 * 4]);
        }
        __syncthreads();
        const uint32_t bAh = smem_u32(sAh), bAl = smem_u32(sAl);
        const uint32_t bBh = smem_u32(sBh), bBl = smem_u32(sBl);
        const int g = lane >> 3;
#pragma unroll
        for (int kk = 0; kk < 64; kk += 16) {
            uint32_t ah[2][4], al[2][4], bb[8][2];
#pragma unroll
            for (int mi = 0; mi < 2; mi++) {
                uint32_t off = (uint32_t)((wm * 32 + mi * 16 + (lane & 15)) * 72
                                          + kk + (lane >> 4) * 8) * 2;
                ldm_x4(ah[mi], bAh + off);
                if (full) ldm_x4(al[mi], bAl + off);
            }
#pragma unroll
            for (int g4 = 0; g4 < 4; g4++) {          // B hi frags via trans
                uint32_t off = (uint32_t)((kk + (g >> 1) * 8 + (lane & 7)) * 136
                                          + wn * 64 + g4 * 16 + (g & 1) * 8) * 2;
                uint32_t r4[4];
                ldm_x4_t(r4, bBh + off);
                bb[g4 * 2 + 0][0] = r4[0]; bb[g4 * 2 + 0][1] = r4[2];
                bb[g4 * 2 + 1][0] = r4[1]; bb[g4 * 2 + 1][1] = r4[3];
            }
#pragma unroll
            for (int mi = 0; mi < 2; mi++)
#pragma unroll
                for (int o = 0; o < 8; o++)
                    mma_16816(acc[mi][o], ah[mi], bb[o][0], bb[o][1]);
            if (full) {
#pragma unroll
                for (int mi = 0; mi < 2; mi++)
#pragma unroll
                    for (int o = 0; o < 8; o++)
                        mma_16816(acc[mi][o], al[mi], bb[o][0], bb[o][1]);
#pragma unroll
                for (int g4 = 0; g4 < 4; g4++) {      // B lo frags
                    uint32_t off = (uint32_t)((kk + (g >> 1) * 8 + (lane & 7)) * 136
                                              + wn * 64 + g4 * 16 + (g & 1) * 8) * 2;
                    uint32_t r4[4];
                    ldm_x4_t(r4, bBl + off);
                    bb[g4 * 2 + 0][0] = r4[0]; bb[g4 * 2 + 0][1] = r4[2];
                    bb[g4 * 2 + 1][0] = r4[1]; bb[g4 * 2 + 1][1] = r4[3];
                }
#pragma unroll
                for (int mi = 0; mi < 2; mi++)
#pragma unroll
                    for (int o = 0; o < 8; o++)
                        mma_16816(acc[mi][o], ah[mi], bb[o][0], bb[o][1]);
            }
        }
        __syncthreads();
    }
#pragma unroll
    for (int mi = 0; mi < 2; mi++)
#pragma unroll
        for (int o = 0; o < 8; o++)
#pragma unroll
            for (int half = 0; half < 2; half++) {
                int row = m0 + wm * 32 + mi * 16 + (lane >> 2) + half * 8;
                int col = n0 + wn * 64 + o * 8 + (lane & 3) * 2;
                float2 w;
                w.x = acc[mi][o][half * 2 + 0];
                w.y = acc[mi][o][half * 2 + 1];
                *(float2*)&C[(size_t)row * 1024 + col] = w;
            }
}

// K1: q/k/v projections. Q,K plain bf16 (their outputs are bf16-rounded
// anyway and qk error is dominated by exact fp32 prev); V full split.
__global__ void __launch_bounds__(256, 2)
proj_mma_kernel(const float* __restrict__ x, const float* __restrict__ Wq,
                const float* __restrict__ Wk, const float* __restrict__ Wv)
{
    const float* B = (blockIdx.z == 0) ? Wq : (blockIdx.z == 1 ? Wk : Wv);
    gemm_split(x, B, &g_lin[blockIdx.z][0][0], blockIdx.z == 2);
}

// K6: out = g_o @ Wo (full split: propagates linearly to output)
__global__ void __launch_bounds__(256, 2)
out_mma_kernel(const float* __restrict__ Wo, float* __restrict__ out)
{
    gemm_split(&g_o[0][0], Wo, out, true);
}

// K0: zero the row-sum accumulator
__global__ void zero_l_kernel()
{
    g_l[blockIdx.x * 256 + threadIdx.x] = 0.f;
}

// K2: depthwise conv; Q,K as bf16, V fp32
__global__ void conv_kernel(const float* __restrict__ cq,
                            const float* __restrict__ ck,
                            const float* __restrict__ cv)
{
    int idx = blockIdx.x * 256 + threadIdx.x;
    int z   = idx / (NW * NBINS);
    int rem = idx - z * (NW * NBINS);
    int w   = rem >> 10;
    int c   = rem & 1023;
    const float* cw = (z == 0) ? cq : (z == 1 ? ck : cv);
    float w0 = cw[c * 3 + 0], w1 = cw[c * 3 + 1], w2 = cw[c * 3 + 2];
    float acc = g_lin[z][w][c] * w1;
    if (w > 0)      acc += g_lin[z][w - 1][c] * w0;
    if (w < NW - 1) acc += g_lin[z][w + 1][c] * w2;
    if (z == 0)      g_qb[w][c] = __float2bfloat16(acc);
    else if (z == 1) g_kb[w][c] = __float2bfloat16(acc);
    else             g_v[w][c]  = acc;
}

// K2b: relw transpose + bf16 convert
__global__ void relw_cvt_kernel(const float* __restrict__ relw)
{
    int idx = blockIdx.x * 256 + threadIdx.x;   // 64*2048
    int d = idx >> 11, i = idx & 2047;
    g_rwb[i][d] = __float2bfloat16(relw[idx]);
}

// K2c: V -> per-head transposed hi/lo bf16 (tiled 64x64 transpose)
__global__ void __launch_bounds__(256)
vt_split_kernel()
{
    __shared__ float tile[64][65];
    const int w0 = blockIdx.x * 64, h = blockIdx.y;
    const int t = threadIdx.x;
#pragma unroll
    for (int s = 0; s < 4; s++) {
        int e = t + 256 * s;
        int r = e >> 4, c4 = e & 15;
        float4 v = *(const float4*)&g_v[w0 + r][h * 64 + c4 * 4];
        tile[r][c4 * 4 + 0] = v.x; tile[r][c4 * 4 + 1] = v.y;
        tile[r][c4 * 4 + 2] = v.z; tile[r][c4 * 4 + 3] = v.w;
    }
    __syncthreads();
#pragma unroll
    for (int s = 0; s < 4; s++) {
        int e = t + 256 * s;
        int d = e >> 4, w4 = e & 15;
        __nv_bfloat16 hh[4], ll[4];
#pragma unroll
        for (int i = 0; i < 4; i++) {
            float f = tile[w4 * 4 + i][d];
            hh[i] = __float2bfloat16(f);
            ll[i] = __float2bfloat16(f - __bfloat162float(hh[i]));
        }
        *(uint2*)&g_vth[h][d][w0 + w4 * 4] = *(uint2*)hh;
        *(uint2*)&g_vtl[h][d][w0 + w4 * 4] = *(uint2*)ll;
    }
}

// K3: qk via mma.sync bf16; staged coalesced epilogue that ALSO accumulates
// softmax row sums (exp without max: |qk| <~ 1, softmax shift-invariant).
#define QK_RS 72
__global__ void __launch_bounds__(256)
qk_mma_kernel(const float* __restrict__ prev, float* __restrict__ qk)
{
    extern __shared__ __nv_bfloat16 smb[];
    __nv_bfloat16* sQi = smb;
    __nv_bfloat16* sKj = smb + 128 * QK_RS;
    __nv_bfloat16* sQj = smb + 2 * 128 * QK_RS;
    __nv_bfloat16* sRw = smb + 3 * 128 * QK_RS;

    const int t = threadIdx.x, wid = t >> 5, lane = t & 31;
    const int j0 = blockIdx.x * 128, i0 = blockIdx.y * 128, h = blockIdx.z;

    {
        const int r = t & 127;
        const int ch0 = (t >> 7) * 4;
        const uint4* qi = (const uint4*)&g_qb[i0 + r][h * 64];
        const uint4* kj = (const uint4*)&g_kb[j0 + r][h * 64];
        const uint4* qj = (const uint4*)&g_qb[j0 + r][h * 64];
        const uint4* rw = (const uint4*)&g_rwb[i0 + r][0];
#pragma unroll
        for (int c = 0; c < 4; c++) {
            int c16 = ch0 + c;
            *(uint4*)((char*)sQi + r * 144 + c16 * 16) = qi[c16];
            *(uint4*)((char*)sKj + r * 144 + c16 * 16) = kj[c16];
            *(uint4*)((char*)sQj + r * 144 + c16 * 16) = qj[c16];
            *(uint4*)((char*)sRw + r * 144 + c16 * 16) = rw[c16];
        }
    }
    __syncthreads();

    const int wm = wid & 1;
    const int wn = wid >> 1;
    const uint32_t sbQi = smem_u32(sQi), sbKj = smem_u32(sKj);
    const uint32_t sbQj = smem_u32(sQj), sbRw = smem_u32(sRw);

    float c[4][4][4];
#pragma unroll
    for (int mi = 0; mi < 4; mi++)
#pragma unroll
        for (int ni = 0; ni < 4; ni++)
#pragma unroll
            for (int e = 0; e < 4; e++) c[mi][ni][e] = 0.f;

#pragma unroll
    for (int term = 0; term < 2; term++) {
        const uint32_t sbA = term ? sbRw : sbQi;
        const uint32_t sbB = term ? sbQj : sbKj;
#pragma unroll
        for (int ks = 0; ks < 4; ks++) {
            const int kcol = ks * 16 + (lane >> 4) * 8;
            uint32_t a[4][4];
#pragma unroll
            for (int mi = 0; mi < 4; mi++) {
                int row = wm * 64 + mi * 16 + (lane & 15);
                ldm_x4(a[mi], sbA + (uint32_t)(row * 144 + kcol * 2));
            }
            uint32_t b[4][2];
#pragma unroll
            for (int nh = 0; nh < 2; nh++) {
                int row = wn * 32 + nh * 16 + (lane & 15);
                uint32_t r4[4];
                ldm_x4(r4, sbB + (uint32_t)(row * 144 + kcol * 2));
                b[nh * 2 + 0][0] = r4[0]; b[nh * 2 + 0][1] = r4[2];
                b[nh * 2 + 1][0] = r4[1]; b[nh * 2 + 1][1] = r4[3];
            }
#pragma unroll
            for (int mi = 0; mi < 4; mi++)
#pragma unroll
                for (int ni = 0; ni < 4; ni++)
                    mma_16816(c[mi][ni], a[mi], b[ni][0], b[ni][1]);
        }
    }

    // ---- staged epilogue: accumulators -> smem (fragment layout) ----
    __syncthreads();                       // operand tiles are dead; reuse smem
    float* sC = (float*)smb;               // [128][132]
    const float inv = 1.0f / 32.0f;
    const int qr = lane >> 2, qc = (lane & 3) * 2;
#pragma unroll
    for (int mi = 0; mi < 4; mi++)
#pragma unroll
        for (int ni = 0; ni < 4; ni++)
#pragma unroll
            for (int half = 0; half < 2; half++) {
                int row = wm * 64 + mi * 16 + qr + half * 8;
                int col = wn * 32 + ni * 8 + qc;
                float2 w;
                w.x = c[mi][ni][half * 2 + 0] * inv;
                w.y = c[mi][ni][half * 2 + 1] * inv;
                *(float2*)&sC[row * 132 + col] = w;
            }
    __syncthreads();

    // ---- coalesced prev-read + add + qk-write + row-sum accumulate ----
    // per s-iteration, warp wid covers ALL 128 cols of row (8s + wid).
    const size_t base = ((size_t)(h * 2048 + i0)) * 2048 + j0;
#pragma unroll
    for (int s = 0; s < 16; s++) {
        int r = 8 * s + wid;
        size_t off = base + (size_t)r * 2048 + lane * 4;
        float4 p = *(const float4*)&prev[off];
        float4 v = *(const float4*)&sC[r * 132 + lane * 4];
        float4 o;
        o.x = v.x + p.x; o.y = v.y + p.y; o.z = v.z + p.z; o.w = v.w + p.w;
        *(float4*)&qk[off] = o;
        float es = __expf(o.x) + __expf(o.y) + __expf(o.z) + __expf(o.w);
#pragma unroll
        for (int d = 16; d > 0; d >>= 1)
            es += __shfl_xor_sync(0xffffffffu, es, d);
        if (lane == 0) atomicAdd(&g_l[h * 2048 + i0 + r], es);
    }
}

// K5: AV via split-bf16 mma; P = exp(qk) (no max), divide by g_l.
#define AV_SMEM 104448
__global__ void __launch_bounds__(256, 2)
av_mma_kernel(const float* __restrict__ qk)
{
    extern __shared__ __nv_bfloat16 avs[];
    __nv_bfloat16* sPh = avs;                       // [128][136]
    __nv_bfloat16* sPl = avs + 128 * 136;
    __nv_bfloat16* sVh = avs + 2 * 128 * 136;       // [64][136]
    __nv_bfloat16* sVl = avs + 2 * 128 * 136 + 64 * 136;
    const int i0 = blockIdx.x * 128, h = blockIdx.y;
    const int t = threadIdx.x, wid = t >> 5, lane = t & 31;
    const int wm = wid >> 1, wn = wid & 1;          // warp tile 32(m) x 32(n)

    float acc[2][4][4];
#pragma unroll
    for (int mi = 0; mi < 2; mi++)
#pragma unroll
        for (int o = 0; o < 4; o++)
#pragma unroll
            for (int e = 0; e < 4; e++) acc[mi][o][e] = 0.f;

    for (int jb = 0; jb < 16; jb++) {
        const int j0 = jb * 128;
#pragma unroll
        for (int s = 0; s < 16; s++) {              // P = exp(qk), split
            int e = t + 256 * s;
            int r = e >> 5, c4 = e & 31;
            size_t off = ((size_t)(h * 2048 + i0 + r)) * 2048 + j0 + c4 * 4;
            float4 x = *(const float4*)&qk[off];
            float4 p;
            p.x = __expf(x.x); p.y = __expf(x.y);
            p.z = __expf(x.z); p.w = __expf(x.w);
            split_store(p, &sPh[r * 136 + c4 * 4], &sPl[r * 136 + c4 * 4]);
        }
#pragma unroll
        for (int s = 0; s < 8; s++) {               // V^T tiles hi/lo
            int e = t + 256 * s;
            int d = e >> 5, c4 = e & 31;
            *(uint2*)&sVh[d * 136 + c4 * 4] = *(const uint2*)&g_vth[h][d][j0 + c4 * 4];
            *(uint2*)&sVl[d * 136 + c4 * 4] = *(const uint2*)&g_vtl[h][d][j0 + c4 * 4];
        }
        __syncthreads();
        const uint32_t bPh = smem_u32(sPh), bPl = smem_u32(sPl);
        const uint32_t bVh = smem_u32(sVh), bVl = smem_u32(sVl);
#pragma unroll
        for (int kk = 0; kk < 128; kk += 16) {
            uint32_t ah[2][4], al[2][4], bv[4][2];
#pragma unroll
            for (int mi = 0; mi < 2; mi++) {
                uint32_t off = (uint32_t)((wm * 32 + mi * 16 + (lane & 15)) * 136
                                          + kk + (lane >> 4) * 8) * 2;
                ldm_x4(ah[mi], bPh + off);
                ldm_x4(al[mi], bPl + off);
            }
#pragma unroll
            for (int nb = 0; nb < 2; nb++) {        // Vh frags
                uint32_t off = (uint32_t)((wn * 32 + nb * 16 + (lane & 15)) * 136
                                          + kk + (lane >> 4) * 8) * 2;
                uint32_t r4[4];
                ldm_x4(r4, bVh + off);
                bv[nb * 2 + 0][0] = r4[0]; bv[nb * 2 + 0][1] = r4[2];
                bv[nb * 2 + 1][0] = r4[1]; bv[nb * 2 + 1][1] = r4[3];
            }
#pragma unroll
            for (int mi = 0; mi < 2; mi++)
#pragma unroll
                for (int o = 0; o < 4; o++) {
                    mma_16816(acc[mi][o], ah[mi], bv[o][0], bv[o][1]);
                    mma_16816(acc[mi][o], al[mi], bv[o][0], bv[o][1]);
                }
#pragma unroll
            for (int nb = 0; nb < 2; nb++) {        // Vl frags
                uint32_t off = (uint32_t)((wn * 32 + nb * 16 + (lane & 15)) * 136
                                          + kk + (lane >> 4) * 8) * 2;
                uint32_t r4[4];
                ldm_x4(r4, bVl + off);
                bv[nb * 2 + 0][0] = r4[0]; bv[nb * 2 + 0][1] = r4[2];
                bv[nb * 2 + 1][0] = r4[1]; bv[nb * 2 + 1][1] = r4[3];
            }
#pragma unroll
            for (int mi = 0; mi < 2; mi++)
#pragma unroll
                for (int o = 0; o < 4; o++)
                    mma_16816(acc[mi][o], ah[mi], bv[o][0], bv[o][1]);
        }
        __syncthreads();
    }
#pragma unroll
    for (int mi = 0; mi < 2; mi++)
#pragma unroll
        for (int o = 0; o < 4; o++)
#pragma unroll
            for (int half = 0; half < 2; half++) {
                int row = i0 + wm * 32 + mi * 16 + (lane >> 2) + half * 8;
                float invl = 1.0f / g_l[h * 2048 + row];
                int col = h * 64 + wn * 32 + o * 8 + (lane & 3) * 2;
                float2 w;
                w.x = acc[mi][o][half * 2 + 0] * invl;
                w.y = acc[mi][o][half * 2 + 1] * invl;
                *(float2*)&g_o[row][col] = w;
            }
}

// --------------------------------------------------------------------------
extern "C" void kernel_launch(void* const* d_in, const int* in_sizes, int n_in,
                              void* d_out, int out_size)
{
    const float* x    = (const float*)d_in[0];
    const float* prev = (const float*)d_in[1];
    const float* Wq   = (const float*)d_in[2];
    const float* Wk   = (const float*)d_in[3];
    const float* Wv   = (const float*)d_in[4];
    const float* Wo   = (const float*)d_in[5];
    const float* cq   = (const float*)d_in[6];
    const float* ck   = (const float*)d_in[7];
    const float* cv   = (const float*)d_in[8];
    const float* relw = (const float*)d_in[9];

    float* out = (float*)d_out;                 // (1,2048,1024)
    float* qk  = out + (size_t)NW * NBINS;      // (1,16,2048,2048)

    const size_t QK_SMEM = (size_t)4 * 128 * QK_RS * sizeof(__nv_bfloat16); // 73728
    cudaFuncSetAttribute(proj_mma_kernel, cudaFuncAttributeMaxDynamicSharedMemorySize, GS_SMEM);
    cudaFuncSetAttribute(out_mma_kernel,  cudaFuncAttributeMaxDynamicSharedMemorySize, GS_SMEM);
    cudaFuncSetAttribute(qk_mma_kernel,   cudaFuncAttributeMaxDynamicSharedMemorySize, (int)QK_SMEM);
    cudaFuncSetAttribute(av_mma_kernel,   cudaFuncAttributeMaxDynamicSharedMemorySize, AV_SMEM);

    zero_l_kernel<<<(NH * NW) / 256, 256>>>();
    proj_mma_kernel<<<dim3(8, 16, 3), 256, GS_SMEM>>>(x, Wq, Wk, Wv);
    conv_kernel<<<(3 * NW * NBINS) / 256, 256>>>(cq, ck, cv);
    relw_cvt_kernel<<<(HD * NW) / 256, 256>>>(relw);
    vt_split_kernel<<<dim3(32, 16), 256>>>();
    qk_mma_kernel<<<dim3(16, 16, 16), 256, QK_SMEM>>>(prev, qk);
    av_mma_kernel<<<dim3(16, 16), 256, AV_SMEM>>>(qk);
    out_mma_kernel<<<dim3(8, 16), 256, GS_SMEM>>>(Wo, out);
}

// round 11
// speedup vs baseline: 1.6182x; 1.1428x over previous
#include <cuda_runtime.h>
#include <cuda_bf16.h>
#include <math.h>
#include <stdint.h>

#define NW    2048
#define NBINS 1024
#define NH    16
#define HD    64

// ---------------- scratch (device globals: allocation-free) ----------------
__device__ float g_lin[3][NW][NBINS];          // post-projection q/k/v (pre-conv)
__device__ float g_v[NW][NBINS];               // post-conv V fp32
__device__ __nv_bfloat16 g_qb[NW][NBINS];      // post-conv Q, bf16
__device__ __nv_bfloat16 g_kb[NW][NBINS];      // post-conv K, bf16
__device__ __nv_bfloat16 g_rwb[NW][HD];        // relw^T bf16
__device__ __nv_bfloat16 g_vth[NH][HD][NW];    // V^T per head, hi part
__device__ __nv_bfloat16 g_vtl[NH][HD][NW];    // V^T per head, lo part
__device__ float g_l[NH * NW];                 // softmax row sum (atomic acc)
// bf16 pre-converted GEMM operands
__device__ __nv_bfloat16 g_xh[NW][NBINS], g_xl[NW][NBINS];       // x hi/lo
__device__ __nv_bfloat16 g_wqh[NBINS][NBINS], g_wkh[NBINS][NBINS];
__device__ __nv_bfloat16 g_wvh[NBINS][NBINS], g_wvl[NBINS][NBINS];
__device__ __nv_bfloat16 g_woh[NBINS][NBINS], g_wol[NBINS][NBINS];
__device__ __nv_bfloat16 g_oh[NW][NBINS], g_ol[NW][NBINS];       // attn out hi/lo

// ======================= PTX helpers (generic sm_80+) ======================
__device__ __forceinline__ uint32_t smem_u32(const void* p) {
    uint32_t a;
    asm("{ .reg .u64 t; cvta.to.shared.u64 t, %1; cvt.u32.u64 %0, t; }"
        : "=r"(a) : "l"(p));
    return a;
}
__device__ __forceinline__ void ldm_x4(uint32_t r[4], uint32_t addr) {
    asm volatile("ldmatrix.sync.aligned.m8n8.x4.shared.b16 {%0,%1,%2,%3}, [%4];"
                 : "=r"(r[0]), "=r"(r[1]), "=r"(r[2]), "=r"(r[3]) : "r"(addr));
}
__device__ __forceinline__ void ldm_x4_t(uint32_t r[4], uint32_t addr) {
    asm volatile("ldmatrix.sync.aligned.m8n8.x4.trans.shared.b16 {%0,%1,%2,%3}, [%4];"
                 : "=r"(r[0]), "=r"(r[1]), "=r"(r[2]), "=r"(r[3]) : "r"(addr));
}
__device__ __forceinline__ void mma_16816(float c[4], const uint32_t a[4],
                                          uint32_t b0, uint32_t b1) {
    asm volatile(
        "mma.sync.aligned.m16n8k16.row.col.f32.bf16.bf16.f32 "
        "{%0,%1,%2,%3}, {%4,%5,%6,%7}, {%8,%9}, {%0,%1,%2,%3};"
        : "+f"(c[0]), "+f"(c[1]), "+f"(c[2]), "+f"(c[3])
        : "r"(a[0]), "r"(a[1]), "r"(a[2]), "r"(a[3]), "r"(b0), "r"(b1));
}
#define CP16(dst, src) \
    asm volatile("cp.async.cg.shared.global [%0], [%1], 16;" \
                 :: "r"(dst), "l"(src))
#define CP_COMMIT() asm volatile("cp.async.commit_group;")
#define CP_WAIT1()  asm volatile("cp.async.wait_group 1;")
#define CP_WAIT0()  asm volatile("cp.async.wait_group 0;")

// split a float4 into hi/lo bf16 quads and store (8B each)
__device__ __forceinline__ void split_store(float4 v, __nv_bfloat16* ph,
                                            __nv_bfloat16* pl) {
    __nv_bfloat16 hh[4], ll[4];
#pragma unroll
    for (int i = 0; i < 4; i++) {
        float f = (&v.x)[i];
        hh[i] = __float2bfloat16(f);
        ll[i] = __float2bfloat16(f - __bfloat162float(hh[i]));
    }
    *(uint2*)ph = *(uint2*)hh;
    *(uint2*)pl = *(uint2*)ll;
}
__device__ __forceinline__ void hi_store(float4 v, __nv_bfloat16* ph) {
    __nv_bfloat16 hh[4];
#pragma unroll
    for (int i = 0; i < 4; i++) hh[i] = __float2bfloat16((&v.x)[i]);
    *(uint2*)ph = *(uint2*)hh;
}

// ===== pipelined bf16 GEMM: C = A(2048x1024) @ B(1024x1024), 2-stage cp.async
// A row-major bf16 hi(+lo); B k-major [k][n] bf16 hi(+lo); C fp32.
// FULL: 3-term split (Ah·Bh + Al·Bh + Ah·Bl); else hi-only.
#define GP_A_SZ  (128 * 40)     // [128][40] bf16 (32 k-cols + pad)
#define GP_B_SZ  (32 * 136)     // [32][136] bf16 (128 n-cols + pad)
#define GP_SMEM_HI   (2 * (GP_A_SZ + GP_B_SZ) * 2)           // 37888 B
#define GP_SMEM_FULL (2 * (2 * GP_A_SZ + 2 * GP_B_SZ) * 2)   // 75776 B

template <bool FULL>
__global__ void __launch_bounds__(256, 2)
gemm_pipe_kernel(const __nv_bfloat16* __restrict__ Ahp,
                 const __nv_bfloat16* __restrict__ Alp,
                 const __nv_bfloat16* __restrict__ Bhp,
                 const __nv_bfloat16* __restrict__ Blp,
                 float* __restrict__ C)
{
    extern __shared__ __nv_bfloat16 ps[];
    const int STAGE = FULL ? (2 * GP_A_SZ + 2 * GP_B_SZ) : (GP_A_SZ + GP_B_SZ);
    const int OFF_AL = GP_A_SZ;
    const int OFF_BH = FULL ? 2 * GP_A_SZ : GP_A_SZ;
    const int OFF_BL = 2 * GP_A_SZ + GP_B_SZ;

    const int t = threadIdx.x, wid = t >> 5, lane = t & 31;
    const int m0 = blockIdx.y * 128, n0 = blockIdx.x * 128;
    const int wm = wid >> 1, wn = wid & 1;  // warp tile 32(m) x 64(n)

    float acc[2][8][4];
#pragma unroll
    for (int mi = 0; mi < 2; mi++)
#pragma unroll
        for (int o = 0; o < 8; o++)
#pragma unroll
            for (int e = 0; e < 4; e++) acc[mi][o][e] = 0.f;

    const uint32_t sbase = smem_u32(ps);

    // issue cp.async loads for k-iter ki into stage s
    auto load_stage = [&](int ki, int s) {
        const int kb = ki * 32;
        const uint32_t st = sbase + (uint32_t)(s * STAGE) * 2;
#pragma unroll
        for (int u4 = 0; u4 < 2; u4++) {          // A hi: 512 x 16B
            int u = t + 256 * u4;
            int r = u >> 2, c = u & 3;
            CP16(st + (uint32_t)(r * 40 + c * 8) * 2,
                 Ahp + (size_t)(m0 + r) * 1024 + kb + c * 8);
        }
#pragma unroll
        for (int u4 = 0; u4 < 2; u4++) {          // B hi: 512 x 16B
            int u = t + 256 * u4;
            int r = u >> 4, c = u & 15;
            CP16(st + (uint32_t)(OFF_BH + r * 136 + c * 8) * 2,
                 Bhp + (size_t)(kb + r) * 1024 + n0 + c * 8);
        }
        if (FULL) {
#pragma unroll
            for (int u4 = 0; u4 < 2; u4++) {      // A lo
                int u = t + 256 * u4;
                int r = u >> 2, c = u & 3;
                CP16(st + (uint32_t)(OFF_AL + r * 40 + c * 8) * 2,
                     Alp + (size_t)(m0 + r) * 1024 + kb + c * 8);
            }
#pragma unroll
            for (int u4 = 0; u4 < 2; u4++) {      // B lo
                int u = t + 256 * u4;
                int r = u >> 4, c = u & 15;
                CP16(st + (uint32_t)(OFF_BL + r * 136 + c * 8) * 2,
                     Blp + (size_t)(kb + r) * 1024 + n0 + c * 8);
            }
        }
    };

    load_stage(0, 0);
    CP_COMMIT();

    const int g = lane >> 3;
    for (int ki = 0; ki < 32; ki++) {
        const int s = ki & 1;
        if (ki < 31) {
            load_stage(ki + 1, s ^ 1);
            CP_COMMIT();
            CP_WAIT1();
        } else {
            CP_WAIT0();
        }
        __syncthreads();

        const uint32_t bAh = sbase + (uint32_t)(s * STAGE) * 2;
        const uint32_t bAl = bAh + (uint32_t)OFF_AL * 2;
        const uint32_t bBh = sbase + (uint32_t)(s * STAGE + OFF_BH) * 2;
        const uint32_t bBl = sbase + (uint32_t)(s * STAGE + OFF_BL) * 2;
#pragma unroll
        for (int kk = 0; kk < 32; kk += 16) {
            uint32_t ah[2][4], al[2][4], bb[8][2];
#pragma unroll
            for (int mi = 0; mi < 2; mi++) {
                uint32_t off = (uint32_t)((wm * 32 + mi * 16 + (lane & 15)) * 40
                                          + kk + (lane >> 4) * 8) * 2;
                ldm_x4(ah[mi], bAh + off);
                if (FULL) ldm_x4(al[mi], bAl + off);
            }
#pragma unroll
            for (int g4 = 0; g4 < 4; g4++) {      // B hi frags via trans
                uint32_t off = (uint32_t)((kk + (g >> 1) * 8 + (lane & 7)) * 136
                                          + wn * 64 + g4 * 16 + (g & 1) * 8) * 2;
                uint32_t r4[4];
                ldm_x4_t(r4, bBh + off);
                bb[g4 * 2 + 0][0] = r4[0]; bb[g4 * 2 + 0][1] = r4[2];
                bb[g4 * 2 + 1][0] = r4[1]; bb[g4 * 2 + 1][1] = r4[3];
            }
#pragma unroll
            for (int mi = 0; mi < 2; mi++)
#pragma unroll
                for (int o = 0; o < 8; o++)
                    mma_16816(acc[mi][o], ah[mi], bb[o][0], bb[o][1]);
            if (FULL) {
#pragma unroll
                for (int mi = 0; mi < 2; mi++)
#pragma unroll
                    for (int o = 0; o < 8; o++)
                        mma_16816(acc[mi][o], al[mi], bb[o][0], bb[o][1]);
#pragma unroll
                for (int g4 = 0; g4 < 4; g4++) {  // B lo frags
                    uint32_t off = (uint32_t)((kk + (g >> 1) * 8 + (lane & 7)) * 136
                                              + wn * 64 + g4 * 16 + (g & 1) * 8) * 2;
                    uint32_t r4[4];
                    ldm_x4_t(r4, bBl + off);
                    bb[g4 * 2 + 0][0] = r4[0]; bb[g4 * 2 + 0][1] = r4[2];
                    bb[g4 * 2 + 1][0] = r4[1]; bb[g4 * 2 + 1][1] = r4[3];
                }
#pragma unroll
                for (int mi = 0; mi < 2; mi++)
#pragma unroll
                    for (int o = 0; o < 8; o++)
                        mma_16816(acc[mi][o], ah[mi], bb[o][0], bb[o][1]);
            }
        }
        __syncthreads();
    }

#pragma unroll
    for (int mi = 0; mi < 2; mi++)
#pragma unroll
        for (int o = 0; o < 8; o++)
#pragma unroll
            for (int half = 0; half < 2; half++) {
                int row = m0 + wm * 32 + mi * 16 + (lane >> 2) + half * 8;
                int col = n0 + wn * 64 + o * 8 + (lane & 3) * 2;
                float2 w;
                w.x = acc[mi][o][half * 2 + 0];
                w.y = acc[mi][o][half * 2 + 1];
                *(float2*)&C[(size_t)row * 1024 + col] = w;
            }
}

// K0: zero the row-sum accumulator
__global__ void zero_l_kernel()
{
    g_l[blockIdx.x * 256 + threadIdx.x] = 0.f;
}

// K0b: x -> bf16 hi/lo
__global__ void cvt_x_kernel(const float* __restrict__ x)
{
    int i4 = blockIdx.x * 256 + threadIdx.x;     // 2048*1024/4 float4s
    float4 v = ((const float4*)x)[i4];
    split_store(v, &g_xh[0][0] + i4 * 4, &g_xl[0][0] + i4 * 4);
}

// K0c: weights -> bf16 (Wq,Wk hi only; Wv,Wo hi+lo)
__global__ void cvt_w_kernel(const float* __restrict__ Wq, const float* __restrict__ Wk,
                             const float* __restrict__ Wv, const float* __restrict__ Wo)
{
    int z  = blockIdx.y;
    int i4 = blockIdx.x * 256 + threadIdx.x;     // 1024*1024/4
    const float* src = (z == 0) ? Wq : (z == 1) ? Wk : (z == 2) ? Wv : Wo;
    float4 v = ((const float4*)src)[i4];
    if (z == 0)      hi_store(v, &g_wqh[0][0] + i4 * 4);
    else if (z == 1) hi_store(v, &g_wkh[0][0] + i4 * 4);
    else if (z == 2) split_store(v, &g_wvh[0][0] + i4 * 4, &g_wvl[0][0] + i4 * 4);
    else             split_store(v, &g_woh[0][0] + i4 * 4, &g_wol[0][0] + i4 * 4);
}

// K2: depthwise conv; Q,K as bf16, V fp32
__global__ void conv_kernel(const float* __restrict__ cq,
                            const float* __restrict__ ck,
                            const float* __restrict__ cv)
{
    int idx = blockIdx.x * 256 + threadIdx.x;
    int z   = idx / (NW * NBINS);
    int rem = idx - z * (NW * NBINS);
    int w   = rem >> 10;
    int c   = rem & 1023;
    const float* cw = (z == 0) ? cq : (z == 1 ? ck : cv);
    float w0 = cw[c * 3 + 0], w1 = cw[c * 3 + 1], w2 = cw[c * 3 + 2];
    float acc = g_lin[z][w][c] * w1;
    if (w > 0)      acc += g_lin[z][w - 1][c] * w0;
    if (w < NW - 1) acc += g_lin[z][w + 1][c] * w2;
    if (z == 0)      g_qb[w][c] = __float2bfloat16(acc);
    else if (z == 1) g_kb[w][c] = __float2bfloat16(acc);
    else             g_v[w][c]  = acc;
}

// K2b: relw transpose + bf16 convert
__global__ void relw_cvt_kernel(const float* __restrict__ relw)
{
    int idx = blockIdx.x * 256 + threadIdx.x;   // 64*2048
    int d = idx >> 11, i = idx & 2047;
    g_rwb[i][d] = __float2bfloat16(relw[idx]);
}

// K2c: V -> per-head transposed hi/lo bf16 (tiled 64x64 transpose)
__global__ void __launch_bounds__(256)
vt_split_kernel()
{
    __shared__ float tile[64][65];
    const int w0 = blockIdx.x * 64, h = blockIdx.y;
    const int t = threadIdx.x;
#pragma unroll
    for (int s = 0; s < 4; s++) {
        int e = t + 256 * s;
        int r = e >> 4, c4 = e & 15;
        float4 v = *(const float4*)&g_v[w0 + r][h * 64 + c4 * 4];
        tile[r][c4 * 4 + 0] = v.x; tile[r][c4 * 4 + 1] = v.y;
        tile[r][c4 * 4 + 2] = v.z; tile[r][c4 * 4 + 3] = v.w;
    }
    __syncthreads();
#pragma unroll
    for (int s = 0; s < 4; s++) {
        int e = t + 256 * s;
        int d = e >> 4, w4 = e & 15;
        __nv_bfloat16 hh[4], ll[4];
#pragma unroll
        for (int i = 0; i < 4; i++) {
            float f = tile[w4 * 4 + i][d];
            hh[i] = __float2bfloat16(f);
            ll[i] = __float2bfloat16(f - __bfloat162float(hh[i]));
        }
        *(uint2*)&g_vth[h][d][w0 + w4 * 4] = *(uint2*)hh;
        *(uint2*)&g_vtl[h][d][w0 + w4 * 4] = *(uint2*)ll;
    }
}

// K3: qk via mma.sync bf16; staged coalesced epilogue with fused row sums.
#define QK_RS 72
__global__ void __launch_bounds__(256)
qk_mma_kernel(const float* __restrict__ prev, float* __restrict__ qk)
{
    extern __shared__ __nv_bfloat16 smb[];
    __nv_bfloat16* sQi = smb;
    __nv_bfloat16* sKj = smb + 128 * QK_RS;
    __nv_bfloat16* sQj = smb + 2 * 128 * QK_RS;
    __nv_bfloat16* sRw = smb + 3 * 128 * QK_RS;

    const int t = threadIdx.x, wid = t >> 5, lane = t & 31;
    const int j0 = blockIdx.x * 128, i0 = blockIdx.y * 128, h = blockIdx.z;

    {
        const int r = t & 127;
        const int ch0 = (t >> 7) * 4;
        const uint4* qi = (const uint4*)&g_qb[i0 + r][h * 64];
        const uint4* kj = (const uint4*)&g_kb[j0 + r][h * 64];
        const uint4* qj = (const uint4*)&g_qb[j0 + r][h * 64];
        const uint4* rw = (const uint4*)&g_rwb[i0 + r][0];
#pragma unroll
        for (int c = 0; c < 4; c++) {
            int c16 = ch0 + c;
            *(uint4*)((char*)sQi + r * 144 + c16 * 16) = qi[c16];
            *(uint4*)((char*)sKj + r * 144 + c16 * 16) = kj[c16];
            *(uint4*)((char*)sQj + r * 144 + c16 * 16) = qj[c16];
            *(uint4*)((char*)sRw + r * 144 + c16 * 16) = rw[c16];
        }
    }
    __syncthreads();

    const int wm = wid & 1;
    const int wn = wid >> 1;
    const uint32_t sbQi = smem_u32(sQi), sbKj = smem_u32(sKj);
    const uint32_t sbQj = smem_u32(sQj), sbRw = smem_u32(sRw);

    float c[4][4][4];
#pragma unroll
    for (int mi = 0; mi < 4; mi++)
#pragma unroll
        for (int ni = 0; ni < 4; ni++)
#pragma unroll
            for (int e = 0; e < 4; e++) c[mi][ni][e] = 0.f;

#pragma unroll
    for (int term = 0; term < 2; term++) {
        const uint32_t sbA = term ? sbRw : sbQi;
        const uint32_t sbB = term ? sbQj : sbKj;
#pragma unroll
        for (int ks = 0; ks < 4; ks++) {
            const int kcol = ks * 16 + (lane >> 4) * 8;
            uint32_t a[4][4];
#pragma unroll
            for (int mi = 0; mi < 4; mi++) {
                int row = wm * 64 + mi * 16 + (lane & 15);
                ldm_x4(a[mi], sbA + (uint32_t)(row * 144 + kcol * 2));
            }
            uint32_t b[4][2];
#pragma unroll
            for (int nh = 0; nh < 2; nh++) {
                int row = wn * 32 + nh * 16 + (lane & 15);
                uint32_t r4[4];
                ldm_x4(r4, sbB + (uint32_t)(row * 144 + kcol * 2));
                b[nh * 2 + 0][0] = r4[0]; b[nh * 2 + 0][1] = r4[2];
                b[nh * 2 + 1][0] = r4[1]; b[nh * 2 + 1][1] = r4[3];
            }
#pragma unroll
            for (int mi = 0; mi < 4; mi++)
#pragma unroll
                for (int ni = 0; ni < 4; ni++)
                    mma_16816(c[mi][ni], a[mi], b[ni][0], b[ni][1]);
        }
    }

    // ---- staged epilogue: accumulators -> smem (fragment layout) ----
    __syncthreads();
    float* sC = (float*)smb;               // [128][132]
    const float inv = 1.0f / 32.0f;
    const int qr = lane >> 2, qc = (lane & 3) * 2;
#pragma unroll
    for (int mi = 0; mi < 4; mi++)
#pragma unroll
        for (int ni = 0; ni < 4; ni++)
#pragma unroll
            for (int half = 0; half < 2; half++) {
                int row = wm * 64 + mi * 16 + qr + half * 8;
                int col = wn * 32 + ni * 8 + qc;
                float2 w;
                w.x = c[mi][ni][half * 2 + 0] * inv;
                w.y = c[mi][ni][half * 2 + 1] * inv;
                *(float2*)&sC[row * 132 + col] = w;
            }
    __syncthreads();

    const size_t base = ((size_t)(h * 2048 + i0)) * 2048 + j0;
#pragma unroll
    for (int s = 0; s < 16; s++) {
        int r = 8 * s + wid;
        size_t off = base + (size_t)r * 2048 + lane * 4;
        float4 p = *(const float4*)&prev[off];
        float4 v = *(const float4*)&sC[r * 132 + lane * 4];
        float4 o;
        o.x = v.x + p.x; o.y = v.y + p.y; o.z = v.z + p.z; o.w = v.w + p.w;
        *(float4*)&qk[off] = o;
        float es = __expf(o.x) + __expf(o.y) + __expf(o.z) + __expf(o.w);
#pragma unroll
        for (int d = 16; d > 0; d >>= 1)
            es += __shfl_xor_sync(0xffffffffu, es, d);
        if (lane == 0) atomicAdd(&g_l[h * 2048 + i0 + r], es);
    }
}

// K5: AV via split-bf16 mma; P = exp(qk), divide by g_l; writes g_oh/g_ol.
#define AV_SMEM 104448
__global__ void __launch_bounds__(256, 2)
av_mma_kernel(const float* __restrict__ qk)
{
    extern __shared__ __nv_bfloat16 avs[];
    __nv_bfloat16* sPh = avs;                       // [128][136]
    __nv_bfloat16* sPl = avs + 128 * 136;
    __nv_bfloat16* sVh = avs + 2 * 128 * 136;       // [64][136]
    __nv_bfloat16* sVl = avs + 2 * 128 * 136 + 64 * 136;
    const int i0 = blockIdx.x * 128, h = blockIdx.y;
    const int t = threadIdx.x, wid = t >> 5, lane = t & 31;
    const int wm = wid >> 1, wn = wid & 1;          // warp tile 32(m) x 32(n)

    float acc[2][4][4];
#pragma unroll
    for (int mi = 0; mi < 2; mi++)
#pragma unroll
        for (int o = 0; o < 4; o++)
#pragma unroll
            for (int e = 0; e < 4; e++) acc[mi][o][e] = 0.f;

    for (int jb = 0; jb < 16; jb++) {
        const int j0 = jb * 128;
#pragma unroll
        for (int s = 0; s < 16; s++) {              // P = exp(qk), split
            int e = t + 256 * s;
            int r = e >> 5, c4 = e & 31;
            size_t off = ((size_t)(h * 2048 + i0 + r)) * 2048 + j0 + c4 * 4;
            float4 x = *(const float4*)&qk[off];
            float4 p;
            p.x = __expf(x.x); p.y = __expf(x.y);
            p.z = __expf(x.z); p.w = __expf(x.w);
            split_store(p, &sPh[r * 136 + c4 * 4], &sPl[r * 136 + c4 * 4]);
        }
#pragma unroll
        for (int s = 0; s < 8; s++) {               // V^T tiles hi/lo
            int e = t + 256 * s;
            int d = e >> 5, c4 = e & 31;
            *(uint2*)&sVh[d * 136 + c4 * 4] = *(const uint2*)&g_vth[h][d][j0 + c4 * 4];
            *(uint2*)&sVl[d * 136 + c4 * 4] = *(const uint2*)&g_vtl[h][d][j0 + c4 * 4];
        }
        __syncthreads();
        const uint32_t bPh = smem_u32(sPh), bPl = smem_u32(sPl);
        const uint32_t bVh = smem_u32(sVh), bVl = smem_u32(sVl);
#pragma unroll
        for (int kk = 0; kk < 128; kk += 16) {
            uint32_t ah[2][4], al[2][4], bv[4][2];
#pragma unroll
            for (int mi = 0; mi < 2; mi++) {
                uint32_t off = (uint32_t)((wm * 32 + mi * 16 + (lane & 15)) * 136
                                          + kk + (lane >> 4) * 8) * 2;
                ldm_x4(ah[mi], bPh + off);
                ldm_x4(al[mi], bPl + off);
            }
#pragma unroll
            for (int nb = 0; nb < 2; nb++) {        // Vh frags
                uint32_t off = (uint32_t)((wn * 32 + nb * 16 + (lane & 15)) * 136
                                          + kk + (lane >> 4) * 8) * 2;
                uint32_t r4[4];
                ldm_x4(r4, bVh + off);
                bv[nb * 2 + 0][0] = r4[0]; bv[nb * 2 + 0][1] = r4[2];
                bv[nb * 2 + 1][0] = r4[1]; bv[nb * 2 + 1][1] = r4[3];
            }
#pragma unroll
            for (int mi = 0; mi < 2; mi++)
#pragma unroll
                for (int o = 0; o < 4; o++) {
                    mma_16816(acc[mi][o], ah[mi], bv[o][0], bv[o][1]);
                    mma_16816(acc[mi][o], al[mi], bv[o][0], bv[o][1]);
                }
#pragma unroll
            for (int nb = 0; nb < 2; nb++) {        // Vl frags
                uint32_t off = (uint32_t)((wn * 32 + nb * 16 + (lane & 15)) * 136
                                          + kk + (lane >> 4) * 8) * 2;
                uint32_t r4[4];
                ldm_x4(r4, bVl + off);
                bv[nb * 2 + 0][0] = r4[0]; bv[nb * 2 + 0][1] = r4[2];
                bv[nb * 2 + 1][0] = r4[1]; bv[nb * 2 + 1][1] = r4[3];
            }
#pragma unroll
            for (int mi = 0; mi < 2; mi++)
#pragma unroll
                for (int o = 0; o < 4; o++)
                    mma_16816(acc[mi][o], ah[mi], bv[o][0], bv[o][1]);
        }
        __syncthreads();
    }
#pragma unroll
    for (int mi = 0; mi < 2; mi++)
#pragma unroll
        for (int o = 0; o < 4; o++)
#pragma unroll
            for (int half = 0; half < 2; half++) {
                int row = i0 + wm * 32 + mi * 16 + (lane >> 2) + half * 8;
                float invl = 1.0f / g_l[h * 2048 + row];
                int col = h * 64 + wn * 32 + o * 8 + (lane & 3) * 2;
                float o0 = acc[mi][o][half * 2 + 0] * invl;
                float o1 = acc[mi][o][half * 2 + 1] * invl;
                __nv_bfloat16 h0 = __float2bfloat16(o0);
                __nv_bfloat16 h1 = __float2bfloat16(o1);
                __nv_bfloat16 l0 = __float2bfloat16(o0 - __bfloat162float(h0));
                __nv_bfloat16 l1 = __float2bfloat16(o1 - __bfloat162float(h1));
                __nv_bfloat162 ph; ph.x = h0; ph.y = h1;
                __nv_bfloat162 pl; pl.x = l0; pl.y = l1;
                *(__nv_bfloat162*)&g_oh[row][col] = ph;
                *(__nv_bfloat162*)&g_ol[row][col] = pl;
            }
}

// --------------------------------------------------------------------------
extern "C" void kernel_launch(void* const* d_in, const int* in_sizes, int n_in,
                              void* d_out, int out_size)
{
    const float* x    = (const float*)d_in[0];
    const float* prev = (const float*)d_in[1];
    const float* Wq   = (const float*)d_in[2];
    const float* Wk   = (const float*)d_in[3];
    const float* Wv   = (const float*)d_in[4];
    const float* Wo   = (const float*)d_in[5];
    const float* cq   = (const float*)d_in[6];
    const float* ck   = (const float*)d_in[7];
    const float* cv   = (const float*)d_in[8];
    const float* relw = (const float*)d_in[9];

    float* out = (float*)d_out;                 // (1,2048,1024)
    float* qk  = out + (size_t)NW * NBINS;      // (1,16,2048,2048)

    const size_t QK_SMEM = (size_t)4 * 128 * QK_RS * sizeof(__nv_bfloat16); // 73728
    cudaFuncSetAttribute(gemm_pipe_kernel<false>, cudaFuncAttributeMaxDynamicSharedMemorySize, GP_SMEM_HI);
    cudaFuncSetAttribute(gemm_pipe_kernel<true>,  cudaFuncAttributeMaxDynamicSharedMemorySize, GP_SMEM_FULL);
    cudaFuncSetAttribute(qk_mma_kernel, cudaFuncAttributeMaxDynamicSharedMemorySize, (int)QK_SMEM);
    cudaFuncSetAttribute(av_mma_kernel, cudaFuncAttributeMaxDynamicSharedMemorySize, AV_SMEM);

    // device-global symbol addresses (host side)
    __nv_bfloat16 *xh, *xl, *wqh, *wkh, *wvh, *wvl, *woh, *wol, *oh, *ol;
    float* lin;
    cudaGetSymbolAddress((void**)&xh,  g_xh);
    cudaGetSymbolAddress((void**)&xl,  g_xl);
    cudaGetSymbolAddress((void**)&wqh, g_wqh);
    cudaGetSymbolAddress((void**)&wkh, g_wkh);
    cudaGetSymbolAddress((void**)&wvh, g_wvh);
    cudaGetSymbolAddress((void**)&wvl, g_wvl);
    cudaGetSymbolAddress((void**)&woh, g_woh);
    cudaGetSymbolAddress((void**)&wol, g_wol);
    cudaGetSymbolAddress((void**)&oh,  g_oh);
    cudaGetSymbolAddress((void**)&ol,  g_ol);
    cudaGetSymbolAddress((void**)&lin, g_lin);

    zero_l_kernel<<<(NH * NW) / 256, 256>>>();
    cvt_x_kernel<<<(NW * NBINS) / 1024, 256>>>(x);
    cvt_w_kernel<<<dim3((NBINS * NBINS) / 1024, 4), 256>>>(Wq, Wk, Wv, Wo);

    gemm_pipe_kernel<false><<<dim3(8, 16), 256, GP_SMEM_HI>>>(
        xh, nullptr, wqh, nullptr, lin + 0 * (size_t)NW * NBINS);
    gemm_pipe_kernel<false><<<dim3(8, 16), 256, GP_SMEM_HI>>>(
        xh, nullptr, wkh, nullptr, lin + 1 * (size_t)NW * NBINS);
    gemm_pipe_kernel<true><<<dim3(8, 16), 256, GP_SMEM_FULL>>>(
        xh, xl, wvh, wvl, lin + 2 * (size_t)NW * NBINS);

    conv_kernel<<<(3 * NW * NBINS) / 256, 256>>>(cq, ck, cv);
    relw_cvt_kernel<<<(HD * NW) / 256, 256>>>(relw);
    vt_split_kernel<<<dim3(32, 16), 256>>>();
    qk_mma_kernel<<<dim3(16, 16, 16), 256, QK_SMEM>>>(prev, qk);
    av_mma_kernel<<<dim3(16, 16), 256, AV_SMEM>>>(qk);
    gemm_pipe_kernel<true><<<dim3(8, 16), 256, GP_SMEM_FULL>>>(
        oh, ol, woh, wol, out);
}